// round 1
// baseline (speedup 1.0000x reference)
#include <cuda_runtime.h>
#include <math.h>

// Problem constants
#define BB 64
#define SS 256
#define II 512
#define HH 512
#define GCOLS (4*HH)          // 2048 gate-columns per direction (i,f,g,o)

// ---------------------------------------------------------------------------
// Scratch (device globals: allocation-free rule)
// ---------------------------------------------------------------------------
// Precomputed input projections + bias: gx[dir][t][gatecol][b]
__device__ float g_gx[2][SS][GCOLS][BB];          // 256 MB
// Double-buffered hidden state per direction: g_h[dir][parity][b][h]
__device__ float g_h[2][2][BB][HH];
// Grid barrier state (one barrier per direction)
__device__ unsigned g_bar_count[2];
__device__ unsigned g_bar_gen[2];

struct Ptrs {
    const float* W[2][4];     // [dir][gate: i,f,g(c),o]  shape (I+H, H) row-major
    const float* bias[2][4];  // (H,)
};

// ---------------------------------------------------------------------------
// Kernel A: input projection GEMM
//   gx[d][t][gate*512 + h][b] = bias + sum_i x[b][t][i] * W[d][gate][i][h]
// Block: 128 threads, tile 64 cols x 64 batch, K=512 in chunks of 16.
// ---------------------------------------------------------------------------
__global__ void proj_kernel(const float* __restrict__ x, Ptrs p)
{
    const int ct   = blockIdx.x;        // 0..31  (col tile of 64 within 2048)
    const int t    = blockIdx.y;        // 0..255
    const int d    = blockIdx.z;        // 0..1
    const int gate = ct >> 3;           // 8 tiles of 64 per gate
    const int hbase = (ct & 7) * 64;

    const float* __restrict__ Wg = p.W[d][gate];
    const float* __restrict__ bg = p.bias[d][gate];

    const int tid = threadIdx.x;        // 128
    const int c0  = (tid & 7) * 8;      // 0..56
    const int b0  = (tid >> 3) * 4;     // 0..60

    __shared__ float xs[16][68];        // [k][b], padded
    __shared__ float ws[16][64];        // [k][c]

    float acc[8][4];
#pragma unroll
    for (int u = 0; u < 8; u++)
#pragma unroll
        for (int v = 0; v < 4; v++) acc[u][v] = 0.f;

    for (int k0 = 0; k0 < II; k0 += 16) {
        // x tile, transposed into [k][b]
#pragma unroll
        for (int r = 0; r < 2; r++) {
            int i   = tid + r * 128;    // 0..255
            int b   = i >> 2;
            int kk4 = (i & 3) * 4;
            float4 v = *(const float4*)(x + ((size_t)b * SS + t) * II + k0 + kk4);
            xs[kk4 + 0][b] = v.x;
            xs[kk4 + 1][b] = v.y;
            xs[kk4 + 2][b] = v.z;
            xs[kk4 + 3][b] = v.w;
        }
        // W tile [k][c]
#pragma unroll
        for (int r = 0; r < 8; r++) {
            int i  = tid + r * 128;     // 0..1023
            int kk = i >> 6;
            int c  = i & 63;
            ws[kk][c] = Wg[(size_t)(k0 + kk) * HH + hbase + c];
        }
        __syncthreads();

#pragma unroll
        for (int kk = 0; kk < 16; kk++) {
            float4 w0 = *(const float4*)&ws[kk][c0];
            float4 w1 = *(const float4*)&ws[kk][c0 + 4];
            float4 xb = *(const float4*)&xs[kk][b0];
            float cw[8] = {w0.x, w0.y, w0.z, w0.w, w1.x, w1.y, w1.z, w1.w};
            float xv[4] = {xb.x, xb.y, xb.z, xb.w};
#pragma unroll
            for (int u = 0; u < 8; u++)
#pragma unroll
                for (int v = 0; v < 4; v++)
                    acc[u][v] += cw[u] * xv[v];
        }
        __syncthreads();
    }

    // epilogue: add bias, write gx[d][t][gate*512 + h][b]
#pragma unroll
    for (int u = 0; u < 8; u++) {
        int h = hbase + c0 + u;
        float bb = bg[h];
        int gxcol = gate * HH + h;
        float4 o;
        o.x = acc[u][0] + bb;
        o.y = acc[u][1] + bb;
        o.z = acc[u][2] + bb;
        o.w = acc[u][3] + bb;
        *(float4*)&g_gx[d][t][gxcol][b0] = o;
    }
}

// ---------------------------------------------------------------------------
// Grid barrier across the 64 blocks of one direction
// ---------------------------------------------------------------------------
__device__ __forceinline__ void grid_barrier(int id)
{
    __syncthreads();
    if (threadIdx.x == 0) {
        __threadfence();
        volatile unsigned* vg = &g_bar_gen[id];
        unsigned gen = *vg;
        unsigned arrived = atomicAdd(&g_bar_count[id], 1u);
        if (arrived == 63u) {
            atomicExch(&g_bar_count[id], 0u);
            __threadfence();
            *vg = gen + 1u;
        } else {
            while (*vg == gen) { __nanosleep(64); }
        }
        __threadfence();
    }
    __syncthreads();
}

// ---------------------------------------------------------------------------
// Kernel B: persistent recurrent kernel.
// 128 blocks x 128 threads. Blocks 0..63: forward, 64..127: backward.
// Block z owns h-columns [z*8, z*8+8) for all 4 gates (32 weight cols, 64 KB
// of Wh resident in SMEM for all 256 steps). Cell state c in SMEM.
// Per step: acc = gx + h_prev @ Wh_slice; gate nonlinearity; c,h update;
// publish h_t to global double buffer; grid barrier.
// ---------------------------------------------------------------------------
#define REC_THREADS 128
#define REC_W_FLOATS   (512*32)        // 16384
#define REC_H_FLOATS   (64*65)         // 4160   h tile [k][b] pad 65
#define REC_G_FLOATS   (32*68)         // 2176   gate preacts [c][b] pad 68
#define REC_C_FLOATS   (512)           // c state [b*8+h]
#define REC_SMEM_FLOATS (REC_W_FLOATS + REC_H_FLOATS + REC_G_FLOATS + REC_C_FLOATS)
#define REC_SMEM_BYTES  (REC_SMEM_FLOATS * 4)

__global__ void lstm_rec_kernel(float* __restrict__ out, Ptrs p)
{
    const int blk = blockIdx.x;
    const int d   = blk >> 6;           // direction
    const int z   = blk & 63;           // block within direction
    const int hs0 = z * 8;              // owned h columns
    const int tid = threadIdx.x;

    extern __shared__ float sm[];
    float* w_sm    = sm;                                  // [512][32]
    float* h_sm    = w_sm + REC_W_FLOATS;                 // [64][65]  ([k][b])
    float* gate_sm = h_sm + REC_H_FLOATS;                 // [32][68]  ([c][b])
    float* c_sm    = gate_sm + REC_G_FLOATS;              // [512]     (b*8+h)

    // Load recurrent weight slice: w_sm[k][g*8+j] = W[d][g][(512+k)*512 + hs0+j]
    for (int i = tid; i < REC_W_FLOATS; i += REC_THREADS) {
        int k = i >> 5;
        int c = i & 31;
        int g = c >> 3;
        int j = c & 7;
        w_sm[k * 32 + c] = p.W[d][g][(size_t)(II + k) * HH + hs0 + j];
    }
    // Zero cell state and h buffer 0 (this block's columns)
    for (int i = tid; i < 512; i += REC_THREADS) c_sm[i] = 0.f;
    for (int i = tid; i < 512; i += REC_THREADS) {
        int b = i >> 3;
        int j = i & 7;
        g_h[d][0][b][hs0 + j] = 0.f;
    }
    __threadfence();
    grid_barrier(d);

    const int c0 = (tid & 7) * 4;       // 0..28  (4 cols, within one gate)
    const int b0 = (tid >> 3) * 4;      // 0..60

    for (int s = 0; s < SS; s++) {
        const int t  = d ? (SS - 1 - s) : s;
        const int pr = s & 1;
        const int pw = pr ^ 1;

        // Initialize accumulators from precomputed input projection
        float acc[4][4];
#pragma unroll
        for (int u = 0; u < 4; u++) {
            int c = c0 + u;
            int gxcol = (c >> 3) * HH + hs0 + (c & 7);
            float4 v = *(const float4*)&g_gx[d][t][gxcol][b0];
            acc[u][0] = v.x; acc[u][1] = v.y; acc[u][2] = v.z; acc[u][3] = v.w;
        }

        // Recurrent GEMM: acc += h_prev(64x512) @ Wslice(512x32)
        const float* __restrict__ hsrc = &g_h[d][pr][0][0];
        for (int k0 = 0; k0 < HH; k0 += 64) {
            __syncthreads();            // previous tile fully consumed
#pragma unroll 8
            for (int i = tid; i < 64 * 64; i += REC_THREADS) {
                int b = i >> 6;
                int k = i & 63;
                h_sm[k * 65 + b] = hsrc[b * HH + k0 + k];
            }
            __syncthreads();
#pragma unroll 16
            for (int k = 0; k < 64; k++) {
                float4 w4 = *(const float4*)&w_sm[(k0 + k) * 32 + c0];
                float wv[4] = {w4.x, w4.y, w4.z, w4.w};
                float hv[4];
#pragma unroll
                for (int v = 0; v < 4; v++) hv[v] = h_sm[k * 65 + b0 + v];
#pragma unroll
                for (int u = 0; u < 4; u++)
#pragma unroll
                    for (int v = 0; v < 4; v++)
                        acc[u][v] += wv[u] * hv[v];
            }
        }

        // Publish gate preactivations to SMEM for the elementwise phase
        __syncthreads();
#pragma unroll
        for (int u = 0; u < 4; u++) {
            float4 o;
            o.x = acc[u][0]; o.y = acc[u][1]; o.z = acc[u][2]; o.w = acc[u][3];
            *(float4*)&gate_sm[(c0 + u) * 68 + b0] = o;
        }
        __syncthreads();

        // Elementwise LSTM cell update for 64 b x 8 h outputs
#pragma unroll
        for (int r = 0; r < 4; r++) {
            int e  = tid + r * REC_THREADS;   // 0..511
            int b  = e >> 3;
            int hh = e & 7;
            float iv = gate_sm[(0 * 8 + hh) * 68 + b];
            float fv = gate_sm[(1 * 8 + hh) * 68 + b];
            float gv = gate_sm[(2 * 8 + hh) * 68 + b];
            float ov = gate_sm[(3 * 8 + hh) * 68 + b];
            iv = 1.f / (1.f + expf(-iv));
            fv = 1.f / (1.f + expf(-fv));
            ov = 1.f / (1.f + expf(-ov));
            gv = tanhf(gv);
            float cn = fv * c_sm[e] + iv * gv;
            c_sm[e] = cn;
            float hn = ov * tanhf(cn);
            g_h[d][pw][b][hs0 + hh] = hn;
            out[((size_t)b * SS + t) * (2 * HH) + d * HH + hs0 + hh] = hn;
        }

        __threadfence();
        grid_barrier(d);
    }
}

// ---------------------------------------------------------------------------
// Launch
// ---------------------------------------------------------------------------
extern "C" void kernel_launch(void* const* d_in, const int* in_sizes, int n_in,
                              void* d_out, int out_size)
{
    (void)in_sizes; (void)n_in; (void)out_size;
    const float* x = (const float*)d_in[0];

    Ptrs p;
    for (int d = 0; d < 2; d++)
        for (int g = 0; g < 4; g++) {
            p.W[d][g]    = (const float*)d_in[1 + d * 8 + 2 * g];
            p.bias[d][g] = (const float*)d_in[1 + d * 8 + 2 * g + 1];
        }

    // Opt in to >48KB dynamic SMEM for the persistent kernel (attribute set,
    // not a stream op: capture-safe; idempotent across calls).
    cudaFuncSetAttribute(lstm_rec_kernel,
                         cudaFuncAttributeMaxDynamicSharedMemorySize,
                         REC_SMEM_BYTES);

    dim3 pgrid(32, 256, 2);
    proj_kernel<<<pgrid, 128>>>(x, p);

    lstm_rec_kernel<<<128, REC_THREADS, REC_SMEM_BYTES>>>((float*)d_out, p);
}

// round 2
// speedup vs baseline: 1.5158x; 1.5158x over previous
#include <cuda_runtime.h>
#include <math.h>

// Problem constants
#define BB 64
#define SS 256
#define II 512
#define HH 512
#define GCOLS (4*HH)          // 2048 gate-columns per direction (i,f,g,o)

// ---------------------------------------------------------------------------
// Scratch (device globals: allocation-free rule)
// ---------------------------------------------------------------------------
__device__ float g_gx[2][SS][GCOLS][BB];          // 256 MB: gx[d][t][gatecol][b]
__device__ float g_h[2][2][BB][HH];               // double-buffered h per dir
__device__ unsigned g_bar_count[2];
__device__ unsigned g_bar_gen[2];

struct Ptrs {
    const float* W[2][4];     // [dir][gate: i,f,g(c),o]  shape (I+H, H) row-major
    const float* bias[2][4];  // (H,)
};

// ---------------------------------------------------------------------------
// Kernel A: input projection GEMM
//   gx[d][t][gate*512 + h][b] = bias + sum_i x[b][t][i] * W[d][gate][i][h]
// Grid (16, 256, 2), 256 threads. Tile: 128 cols x 64 batch, k-chunk 32.
// Per thread: 8 cols x 4 batch = 32 accums; 3 LDS.128 per 32 FFMA.
// ---------------------------------------------------------------------------
__global__ void __launch_bounds__(256, 3) proj_kernel(const float* __restrict__ x, Ptrs p)
{
    const int ct    = blockIdx.x;        // 0..15  (col tile of 128 within 2048)
    const int t     = blockIdx.y;        // 0..255
    const int d     = blockIdx.z;        // 0..1
    const int gate  = ct >> 2;           // 4 tiles of 128 per gate
    const int hbase = (ct & 3) * 128;

    const float* __restrict__ Wg = p.W[d][gate];
    const float* __restrict__ bg = p.bias[d][gate];

    const int tid = threadIdx.x;         // 256
    const int c0  = (tid & 15) * 8;      // 0..120
    const int b0  = (tid >> 4) * 4;      // 0..60

    __shared__ float ws[32][128];        // [k][c]
    __shared__ float xs[32][68];         // [k][b], 68*4B = 272B (16B-multiple)

    float acc[8][4];
#pragma unroll
    for (int u = 0; u < 8; u++)
#pragma unroll
        for (int v = 0; v < 4; v++) acc[u][v] = 0.f;

    for (int k0 = 0; k0 < II; k0 += 32) {
        // x tile: 32k x 64b, transposed into [k][b]
#pragma unroll
        for (int r = 0; r < 2; r++) {
            int i4  = tid + r * 256;     // 0..511 float4 slots
            int b   = i4 >> 3;
            int kk4 = (i4 & 7) * 4;
            float4 v = *(const float4*)(x + ((size_t)b * SS + t) * II + k0 + kk4);
            xs[kk4 + 0][b] = v.x;
            xs[kk4 + 1][b] = v.y;
            xs[kk4 + 2][b] = v.z;
            xs[kk4 + 3][b] = v.w;
        }
        // W tile: 32k x 128c
#pragma unroll
        for (int r = 0; r < 4; r++) {
            int i4 = tid + r * 256;      // 0..1023 float4 slots
            int kk = i4 >> 5;
            int c4 = (i4 & 31) * 4;
            *(float4*)&ws[kk][c4] =
                *(const float4*)(Wg + (size_t)(k0 + kk) * HH + hbase + c4);
        }
        __syncthreads();

#pragma unroll
        for (int kk = 0; kk < 32; kk++) {
            float4 w0 = *(const float4*)&ws[kk][c0];
            float4 w1 = *(const float4*)&ws[kk][c0 + 4];
            float4 xb = *(const float4*)&xs[kk][b0];
            float cw[8] = {w0.x, w0.y, w0.z, w0.w, w1.x, w1.y, w1.z, w1.w};
            float xv[4] = {xb.x, xb.y, xb.z, xb.w};
#pragma unroll
            for (int u = 0; u < 8; u++)
#pragma unroll
                for (int v = 0; v < 4; v++)
                    acc[u][v] += cw[u] * xv[v];
        }
        __syncthreads();
    }

    // epilogue: add bias, write gx[d][t][gate*512 + h][b]
#pragma unroll
    for (int u = 0; u < 8; u++) {
        int h  = hbase + c0 + u;
        float bb = bg[h];
        int gxcol = gate * HH + h;
        float4 o;
        o.x = acc[u][0] + bb;
        o.y = acc[u][1] + bb;
        o.z = acc[u][2] + bb;
        o.w = acc[u][3] + bb;
        *(float4*)&g_gx[d][t][gxcol][b0] = o;
    }
}

// ---------------------------------------------------------------------------
// Grid barrier across the 64 blocks of one direction
// ---------------------------------------------------------------------------
__device__ __forceinline__ void grid_barrier(int id)
{
    __syncthreads();
    if (threadIdx.x == 0) {
        __threadfence();
        volatile unsigned* vg = &g_bar_gen[id];
        unsigned gen = *vg;
        unsigned arrived = atomicAdd(&g_bar_count[id], 1u);
        if (arrived == 63u) {
            atomicExch(&g_bar_count[id], 0u);
            __threadfence();
            *vg = gen + 1u;
        } else {
            while (*vg == gen) { __nanosleep(32); }
        }
        __threadfence();
    }
    __syncthreads();
}

// ---------------------------------------------------------------------------
// Kernel B: persistent recurrent kernel.
// 128 blocks x 256 threads. Blocks 0..63: forward, 64..127: backward.
// Block z owns 32 gate-columns (8 h x 4 gates); Wh slice (512x32 = 64 KB)
// resident in SMEM. Per thread: 4 cols x 2 batch = 8 accums;
// per k: 1 LDS.128 (W) + 1 LDS.64 (h) : 8 FFMA.
// ---------------------------------------------------------------------------
#define RTH 256
#define REC_W_FLOATS   (512*32)        // 16384
#define REC_H_STRIDE   66
#define REC_H_FLOATS   (64*REC_H_STRIDE)
#define REC_G_FLOATS   (32*REC_H_STRIDE)
#define REC_C_FLOATS   (512)
#define REC_SMEM_FLOATS (REC_W_FLOATS + REC_H_FLOATS + REC_G_FLOATS + REC_C_FLOATS)
#define REC_SMEM_BYTES  (REC_SMEM_FLOATS * 4)

__global__ void __launch_bounds__(RTH, 1) lstm_rec_kernel(float* __restrict__ out, Ptrs p)
{
    const int blk = blockIdx.x;
    const int d   = blk >> 6;           // direction
    const int z   = blk & 63;           // block within direction
    const int hs0 = z * 8;              // owned h columns
    const int tid = threadIdx.x;

    extern __shared__ float sm[];
    float* w_sm    = sm;                                  // [512][32]
    float* h_sm    = w_sm + REC_W_FLOATS;                 // [64][66]  ([k][b])
    float* gate_sm = h_sm + REC_H_FLOATS;                 // [32][66]  ([c][b])
    float* c_sm    = gate_sm + REC_G_FLOATS;              // [512]     (b*8+h)

    // Load recurrent weight slice: w_sm[k][g*8+j] = W[d][g][(512+k)*512 + hs0+j]
    for (int i = tid; i < REC_W_FLOATS; i += RTH) {
        int k = i >> 5;
        int c = i & 31;
        int g = c >> 3;
        int j = c & 7;
        w_sm[k * 32 + c] = p.W[d][g][(size_t)(II + k) * HH + hs0 + j];
    }
    // Zero cell state and h buffer 0 (this block's columns)
    for (int i = tid; i < 512; i += RTH) {
        c_sm[i] = 0.f;
        int b = i >> 3;
        int j = i & 7;
        g_h[d][0][b][hs0 + j] = 0.f;
    }
    __threadfence();
    grid_barrier(d);

    const int c0 = (tid & 7) * 4;       // 0..28  (4 gate-cols)
    const int b0 = (tid >> 3) * 2;      // 0..62  (2 batch)

    for (int s = 0; s < SS; s++) {
        const int t  = d ? (SS - 1 - s) : s;
        const int pr = s & 1;
        const int pw = pr ^ 1;

        // Initialize accumulators from precomputed input projection
        float acc[4][2];
#pragma unroll
        for (int u = 0; u < 4; u++) {
            int c = c0 + u;
            int gxcol = (c >> 3) * HH + hs0 + (c & 7);
            float2 v = *(const float2*)&g_gx[d][t][gxcol][b0];
            acc[u][0] = v.x; acc[u][1] = v.y;
        }

        // Recurrent GEMM: acc += h_prev(64x512) @ Wslice(512x32)
        const float* __restrict__ hsrc = &g_h[d][pr][0][0];
        for (int k0 = 0; k0 < HH; k0 += 64) {
            __syncthreads();            // previous tile fully consumed
#pragma unroll
            for (int r = 0; r < 4; r++) {
                int i4 = tid + r * RTH;          // 0..1023 float4 slots
                int b  = i4 >> 4;
                int kk = (i4 & 15) * 4;
                float4 v = *(const float4*)&hsrc[b * HH + k0 + kk];
                h_sm[(kk + 0) * REC_H_STRIDE + b] = v.x;
                h_sm[(kk + 1) * REC_H_STRIDE + b] = v.y;
                h_sm[(kk + 2) * REC_H_STRIDE + b] = v.z;
                h_sm[(kk + 3) * REC_H_STRIDE + b] = v.w;
            }
            __syncthreads();
#pragma unroll 16
            for (int k = 0; k < 64; k++) {
                float4 w4 = *(const float4*)&w_sm[(k0 + k) * 32 + c0];
                float2 hb = *(const float2*)&h_sm[k * REC_H_STRIDE + b0];
                float wv[4] = {w4.x, w4.y, w4.z, w4.w};
#pragma unroll
                for (int u = 0; u < 4; u++) {
                    acc[u][0] += wv[u] * hb.x;
                    acc[u][1] += wv[u] * hb.y;
                }
            }
        }

        // Publish gate preactivations to SMEM for the elementwise phase
        __syncthreads();
#pragma unroll
        for (int u = 0; u < 4; u++) {
            float2 o;
            o.x = acc[u][0]; o.y = acc[u][1];
            *(float2*)&gate_sm[(c0 + u) * REC_H_STRIDE + b0] = o;
        }
        __syncthreads();

        // Elementwise LSTM cell update for 64 b x 8 h outputs
#pragma unroll
        for (int r = 0; r < 2; r++) {
            int e  = tid + r * RTH;     // 0..511
            int b  = e >> 3;
            int hh = e & 7;
            float iv = gate_sm[(0 * 8 + hh) * REC_H_STRIDE + b];
            float fv = gate_sm[(1 * 8 + hh) * REC_H_STRIDE + b];
            float gv = gate_sm[(2 * 8 + hh) * REC_H_STRIDE + b];
            float ov = gate_sm[(3 * 8 + hh) * REC_H_STRIDE + b];
            iv = 1.f / (1.f + expf(-iv));
            fv = 1.f / (1.f + expf(-fv));
            ov = 1.f / (1.f + expf(-ov));
            gv = tanhf(gv);
            float cn = fv * c_sm[e] + iv * gv;
            c_sm[e] = cn;
            float hn = ov * tanhf(cn);
            g_h[d][pw][b][hs0 + hh] = hn;
            out[((size_t)b * SS + t) * (2 * HH) + d * HH + hs0 + hh] = hn;
        }

        __threadfence();
        grid_barrier(d);
    }
}

// ---------------------------------------------------------------------------
// Launch
// ---------------------------------------------------------------------------
extern "C" void kernel_launch(void* const* d_in, const int* in_sizes, int n_in,
                              void* d_out, int out_size)
{
    (void)in_sizes; (void)n_in; (void)out_size;
    const float* x = (const float*)d_in[0];

    Ptrs p;
    for (int d = 0; d < 2; d++)
        for (int g = 0; g < 4; g++) {
            p.W[d][g]    = (const float*)d_in[1 + d * 8 + 2 * g];
            p.bias[d][g] = (const float*)d_in[1 + d * 8 + 2 * g + 1];
        }

    cudaFuncSetAttribute(lstm_rec_kernel,
                         cudaFuncAttributeMaxDynamicSharedMemorySize,
                         REC_SMEM_BYTES);

    dim3 pgrid(16, 256, 2);
    proj_kernel<<<pgrid, 256>>>(x, p);

    lstm_rec_kernel<<<128, RTH, REC_SMEM_BYTES>>>((float*)d_out, p);
}

// round 5
// speedup vs baseline: 1.9612x; 1.2938x over previous
#include <cuda_runtime.h>
#include <cuda_bf16.h>
#include <math.h>
#include <stdint.h>

// Problem constants
#define BB 64
#define SS 256
#define II 512
#define HH 512
#define GCOLS (4*HH)          // 2048 gate-columns per direction (i,f,g,o)

// ---------------------------------------------------------------------------
// Scratch (device globals: allocation-free rule)
// ---------------------------------------------------------------------------
__device__ float g_gx[2][SS][GCOLS][BB];          // 256 MB: gx[d][t][gatecol][b]
__device__ float g_h[2][2][BB][HH];               // double-buffered h per dir
__device__ unsigned g_bar_count[2];
__device__ unsigned g_bar_gen[2];

// bf16 split operands for the tensor-core projection
__device__ __align__(16) __nv_bfloat16 g_xhi[BB * SS * II];      // x hi
__device__ __align__(16) __nv_bfloat16 g_xlo[BB * SS * II];      // x residual
__device__ __align__(16) __nv_bfloat16 g_wthi[2 * 4 * HH * II];  // W^T (input part) hi: [d][g][c][k]
__device__ __align__(16) __nv_bfloat16 g_wtlo[2 * 4 * HH * II];  // W^T lo

struct Ptrs {
    const float* W[2][4];     // [dir][gate: i,f,g(c),o]  shape (I+H, H) row-major
    const float* bias[2][4];  // (H,)
};

// ---------------------------------------------------------------------------
// Split kernels: build bf16 hi/lo operands
// ---------------------------------------------------------------------------
__global__ void split_x_kernel(const float* __restrict__ x)
{
    int n = BB * SS * II;
    for (int i = blockIdx.x * blockDim.x + threadIdx.x; i < n; i += gridDim.x * blockDim.x) {
        float v = x[i];
        __nv_bfloat16 hi = __float2bfloat16(v);
        g_xhi[i] = hi;
        g_xlo[i] = __float2bfloat16(v - __bfloat162float(hi));
    }
}

// Transpose input-part of W (rows 0..511) into [c][k] and split to bf16 hi/lo.
__global__ void split_wt_kernel(Ptrs p)
{
    __shared__ float tile[32][33];
    const int dg = blockIdx.z;           // 0..7
    const int d  = dg >> 2;
    const int g  = dg & 3;
    const int k0 = blockIdx.x * 32;
    const int c0 = blockIdx.y * 32;
    const int tid = threadIdx.x;         // 256
    const int tx = tid & 31;
    const int ty = tid >> 5;             // 0..7

    const float* W = p.W[d][g];
#pragma unroll
    for (int r = 0; r < 4; r++) {
        int k = ty + r * 8;
        tile[k][tx] = W[(size_t)(k0 + k) * HH + c0 + tx];
    }
    __syncthreads();
#pragma unroll
    for (int r = 0; r < 4; r++) {
        int c = ty + r * 8;
        float v = tile[tx][c];
        __nv_bfloat16 hi = __float2bfloat16(v);
        size_t idx = ((size_t)(dg) * HH + c0 + c) * II + k0 + tx;
        g_wthi[idx] = hi;
        g_wtlo[idx] = __float2bfloat16(v - __bfloat162float(hi));
    }
}

// ---------------------------------------------------------------------------
// mma.sync helper (sm_80+ HMMA path; works on base sm_100 target)
// D(16x8) += A(16x16,row) * B(16x8,col), bf16 in, f32 accum.
// ---------------------------------------------------------------------------
__device__ __forceinline__ void mma16816(float* c, const uint32_t* a, const uint32_t* b)
{
    asm volatile(
        "mma.sync.aligned.m16n8k16.row.col.f32.bf16.bf16.f32 "
        "{%0,%1,%2,%3}, {%4,%5,%6,%7}, {%8,%9}, {%0,%1,%2,%3};\n"
        : "+f"(c[0]), "+f"(c[1]), "+f"(c[2]), "+f"(c[3])
        : "r"(a[0]), "r"(a[1]), "r"(a[2]), "r"(a[3]), "r"(b[0]), "r"(b[1]));
}

// ---------------------------------------------------------------------------
// Kernel A: tensor-core input projection via mma.sync (bf16-split, 3 terms)
//   Block: 128 gate-cols x 128 n (2 timesteps x 64 batch), K=512 in 16 chunks
//   of 32. 8 warps as 2(M) x 4(N); warp tile 64x32; 48 HMMA : 48 LDS.32 / k16.
//   gx[d][t][gate*512+col][b] = sum_k Wt[col][k]*x[b,t,k] + bias[col]
// ---------------------------------------------------------------------------
#define PSTR 40   // padded SMEM k-stride (bf16 units): conflict-free fragments

__global__ void __launch_bounds__(256, 2) proj_mma_kernel(Ptrs p)
{
    __shared__ __nv_bfloat16 As[2][128 * PSTR];   // [hi/lo][row*PSTR + k]
    __shared__ __nv_bfloat16 Bs[2][128 * PSTR];

    const int tid  = threadIdx.x;
    const int lane = tid & 31;
    const int wid  = tid >> 5;
    const int wm   = wid >> 2;          // 0..1 (M)
    const int wn   = wid & 3;           // 0..3 (N)
    const int r    = lane >> 2;         // 0..7
    const int qc   = lane & 3;          // 0..3

    const int ct   = blockIdx.x;        // 0..15: col tile of 128 within 2048
    const int tg   = blockIdx.y;        // 0..127: pair of timesteps
    const int d    = blockIdx.z;
    const int gate = ct >> 2;
    const int hb   = (ct & 3) * 128;
    const int t0   = tg * 2;

    const __nv_bfloat16* __restrict__ wthi = &g_wthi[((size_t)(d * 4 + gate) * HH + hb) * II];
    const __nv_bfloat16* __restrict__ wtlo = &g_wtlo[((size_t)(d * 4 + gate) * HH + hb) * II];

    float acc[4][4][4];                 // [mt][nt][frag]
#pragma unroll
    for (int mt = 0; mt < 4; mt++)
#pragma unroll
        for (int nt = 0; nt < 4; nt++)
#pragma unroll
            for (int u = 0; u < 4; u++) acc[mt][nt][u] = 0.f;

    for (int ch = 0; ch < 16; ch++) {
        const int k0 = ch * 32;
        __syncthreads();
        // Stage A: 128 rows x 32 k (hi + lo)
#pragma unroll
        for (int it = 0; it < 2; it++) {
            int q   = tid + it * 256;        // 0..511 float4 slots
            int row = q >> 2;
            int sl  = (q & 3) * 8;
            size_t src = (size_t)row * II + k0 + sl;
            *(float4*)&As[0][row * PSTR + sl] = *(const float4*)(wthi + src);
            *(float4*)&As[1][row * PSTR + sl] = *(const float4*)(wtlo + src);
        }
        // Stage B: 128 n-rows (tl*64+b) x 32 k (hi + lo)
#pragma unroll
        for (int it = 0; it < 2; it++) {
            int q   = tid + it * 256;
            int row = q >> 2;
            int sl  = (q & 3) * 8;
            int b   = row & 63;
            int tl  = row >> 6;
            size_t src = ((size_t)b * SS + t0 + tl) * II + k0 + sl;
            *(float4*)&Bs[0][row * PSTR + sl] = *(const float4*)&g_xhi[src];
            *(float4*)&Bs[1][row * PSTR + sl] = *(const float4*)&g_xlo[src];
        }
        __syncthreads();

#pragma unroll
        for (int s = 0; s < 2; s++) {
            const int kb = s * 16;
            // B fragments for this k16 (all 4 n-tiles, hi and lo)
            uint32_t bh[4][2], bl[4][2];
#pragma unroll
            for (int nt = 0; nt < 4; nt++) {
                int n   = wn * 32 + nt * 8 + r;
                int off = n * PSTR + kb + qc * 2;
                bh[nt][0] = *(const uint32_t*)&Bs[0][off];
                bh[nt][1] = *(const uint32_t*)&Bs[0][off + 8];
                bl[nt][0] = *(const uint32_t*)&Bs[1][off];
                bl[nt][1] = *(const uint32_t*)&Bs[1][off + 8];
            }
#pragma unroll
            for (int mt = 0; mt < 4; mt++) {
                int m   = wm * 64 + mt * 16 + r;
                int off = m * PSTR + kb + qc * 2;
                uint32_t ah[4], al[4];
                ah[0] = *(const uint32_t*)&As[0][off];
                ah[1] = *(const uint32_t*)&As[0][off + 8 * PSTR];
                ah[2] = *(const uint32_t*)&As[0][off + 8];
                ah[3] = *(const uint32_t*)&As[0][off + 8 * PSTR + 8];
                al[0] = *(const uint32_t*)&As[1][off];
                al[1] = *(const uint32_t*)&As[1][off + 8 * PSTR];
                al[2] = *(const uint32_t*)&As[1][off + 8];
                al[3] = *(const uint32_t*)&As[1][off + 8 * PSTR + 8];
#pragma unroll
                for (int nt = 0; nt < 4; nt++) {
                    mma16816(acc[mt][nt], ah, bh[nt]);   // hi*hi
                    mma16816(acc[mt][nt], ah, bl[nt]);   // hi*lo
                    mma16816(acc[mt][nt], al, bh[nt]);   // lo*hi
                }
            }
        }
    }

    // Epilogue: add bias, write g_gx[d][t][gate*512+col][b]
    const float* __restrict__ bias = p.bias[d][gate];
#pragma unroll
    for (int mt = 0; mt < 4; mt++) {
        int col0 = hb + wm * 64 + mt * 16 + r;          // within gate (0..511)
        float bv0 = bias[col0];
        float bv1 = bias[col0 + 8];
#pragma unroll
        for (int nt = 0; nt < 4; nt++) {
            int n  = wn * 32 + nt * 8 + qc * 2;
            int tl = n >> 6;
            int b  = n & 63;
            float2 v0, v1;
            v0.x = acc[mt][nt][0] + bv0;
            v0.y = acc[mt][nt][1] + bv0;
            v1.x = acc[mt][nt][2] + bv1;
            v1.y = acc[mt][nt][3] + bv1;
            *(float2*)&g_gx[d][t0 + tl][gate * 512 + col0][b]     = v0;
            *(float2*)&g_gx[d][t0 + tl][gate * 512 + col0 + 8][b] = v1;
        }
    }
}

// ---------------------------------------------------------------------------
// Grid barrier across the 64 blocks of one direction
// ---------------------------------------------------------------------------
__device__ __forceinline__ void grid_barrier(int id)
{
    __syncthreads();
    if (threadIdx.x == 0) {
        __threadfence();
        volatile unsigned* vg = &g_bar_gen[id];
        unsigned gen = *vg;
        unsigned arrived = atomicAdd(&g_bar_count[id], 1u);
        if (arrived == 63u) {
            atomicExch(&g_bar_count[id], 0u);
            __threadfence();
            *vg = gen + 1u;
        } else {
            while (*vg == gen) { __nanosleep(32); }
        }
        __threadfence();
    }
    __syncthreads();
}

// ---------------------------------------------------------------------------
// Kernel B: persistent recurrent kernel (unchanged from round 2 PASS).
// ---------------------------------------------------------------------------
#define RTH 256
#define REC_W_FLOATS   (512*32)
#define REC_H_STRIDE   66
#define REC_H_FLOATS   (64*REC_H_STRIDE)
#define REC_G_FLOATS   (32*REC_H_STRIDE)
#define REC_C_FLOATS   (512)
#define REC_SMEM_FLOATS (REC_W_FLOATS + REC_H_FLOATS + REC_G_FLOATS + REC_C_FLOATS)
#define REC_SMEM_BYTES  (REC_SMEM_FLOATS * 4)

__global__ void __launch_bounds__(RTH, 1) lstm_rec_kernel(float* __restrict__ out, Ptrs p)
{
    const int blk = blockIdx.x;
    const int d   = blk >> 6;
    const int z   = blk & 63;
    const int hs0 = z * 8;
    const int tid = threadIdx.x;

    extern __shared__ float sm[];
    float* w_sm    = sm;
    float* h_sm    = w_sm + REC_W_FLOATS;
    float* gate_sm = h_sm + REC_H_FLOATS;
    float* c_sm    = gate_sm + REC_G_FLOATS;

    for (int i = tid; i < REC_W_FLOATS; i += RTH) {
        int k = i >> 5;
        int c = i & 31;
        int g = c >> 3;
        int j = c & 7;
        w_sm[k * 32 + c] = p.W[d][g][(size_t)(II + k) * HH + hs0 + j];
    }
    for (int i = tid; i < 512; i += RTH) {
        c_sm[i] = 0.f;
        int b = i >> 3;
        int j = i & 7;
        g_h[d][0][b][hs0 + j] = 0.f;
    }
    __threadfence();
    grid_barrier(d);

    const int c0 = (tid & 7) * 4;
    const int b0 = (tid >> 3) * 2;

    for (int s = 0; s < SS; s++) {
        const int t  = d ? (SS - 1 - s) : s;
        const int pr = s & 1;
        const int pw = pr ^ 1;

        float acc[4][2];
#pragma unroll
        for (int u = 0; u < 4; u++) {
            int c = c0 + u;
            int gxcol = (c >> 3) * HH + hs0 + (c & 7);
            float2 v = *(const float2*)&g_gx[d][t][gxcol][b0];
            acc[u][0] = v.x; acc[u][1] = v.y;
        }

        const float* __restrict__ hsrc = &g_h[d][pr][0][0];
        for (int k0 = 0; k0 < HH; k0 += 64) {
            __syncthreads();
#pragma unroll
            for (int rr = 0; rr < 4; rr++) {
                int i4 = tid + rr * RTH;
                int b  = i4 >> 4;
                int kk = (i4 & 15) * 4;
                float4 v = *(const float4*)&hsrc[b * HH + k0 + kk];
                h_sm[(kk + 0) * REC_H_STRIDE + b] = v.x;
                h_sm[(kk + 1) * REC_H_STRIDE + b] = v.y;
                h_sm[(kk + 2) * REC_H_STRIDE + b] = v.z;
                h_sm[(kk + 3) * REC_H_STRIDE + b] = v.w;
            }
            __syncthreads();
#pragma unroll 16
            for (int k = 0; k < 64; k++) {
                float4 w4 = *(const float4*)&w_sm[(k0 + k) * 32 + c0];
                float2 hb = *(const float2*)&h_sm[k * REC_H_STRIDE + b0];
                float wv[4] = {w4.x, w4.y, w4.z, w4.w};
#pragma unroll
                for (int u = 0; u < 4; u++) {
                    acc[u][0] += wv[u] * hb.x;
                    acc[u][1] += wv[u] * hb.y;
                }
            }
        }

        __syncthreads();
#pragma unroll
        for (int u = 0; u < 4; u++) {
            float2 o;
            o.x = acc[u][0]; o.y = acc[u][1];
            *(float2*)&gate_sm[(c0 + u) * REC_H_STRIDE + b0] = o;
        }
        __syncthreads();

#pragma unroll
        for (int rr = 0; rr < 2; rr++) {
            int e  = tid + rr * RTH;
            int b  = e >> 3;
            int hh = e & 7;
            float iv = gate_sm[(0 * 8 + hh) * REC_H_STRIDE + b];
            float fv = gate_sm[(1 * 8 + hh) * REC_H_STRIDE + b];
            float gv = gate_sm[(2 * 8 + hh) * REC_H_STRIDE + b];
            float ov = gate_sm[(3 * 8 + hh) * REC_H_STRIDE + b];
            iv = 1.f / (1.f + expf(-iv));
            fv = 1.f / (1.f + expf(-fv));
            ov = 1.f / (1.f + expf(-ov));
            gv = tanhf(gv);
            float cn = fv * c_sm[e] + iv * gv;
            c_sm[e] = cn;
            float hn = ov * tanhf(cn);
            g_h[d][pw][b][hs0 + hh] = hn;
            out[((size_t)b * SS + t) * (2 * HH) + d * HH + hs0 + hh] = hn;
        }

        __threadfence();
        grid_barrier(d);
    }
}

// ---------------------------------------------------------------------------
// Launch
// ---------------------------------------------------------------------------
extern "C" void kernel_launch(void* const* d_in, const int* in_sizes, int n_in,
                              void* d_out, int out_size)
{
    (void)in_sizes; (void)n_in; (void)out_size;
    const float* x = (const float*)d_in[0];

    Ptrs p;
    for (int d = 0; d < 2; d++)
        for (int g = 0; g < 4; g++) {
            p.W[d][g]    = (const float*)d_in[1 + d * 8 + 2 * g];
            p.bias[d][g] = (const float*)d_in[1 + d * 8 + 2 * g + 1];
        }

    cudaFuncSetAttribute(lstm_rec_kernel,
                         cudaFuncAttributeMaxDynamicSharedMemorySize,
                         REC_SMEM_BYTES);

    split_x_kernel<<<512, 256>>>(x);
    dim3 wgrid(16, 16, 8);
    split_wt_kernel<<<wgrid, 256>>>(p);

    dim3 pgrid(16, 128, 2);
    proj_mma_kernel<<<pgrid, 256>>>(p);

    lstm_rec_kernel<<<128, RTH, REC_SMEM_BYTES>>>((float*)d_out, p);
}

// round 6
// speedup vs baseline: 3.6916x; 1.8823x over previous
#include <cuda_runtime.h>
#include <cuda_bf16.h>
#include <math.h>
#include <stdint.h>

// Problem constants
#define BB 64
#define SS 256
#define II 512
#define HH 512
#define GCOLS (4*HH)          // 2048 gate-columns per direction (i,f,g,o)

// ---------------------------------------------------------------------------
// Scratch (device globals: allocation-free rule)
// ---------------------------------------------------------------------------
__device__ float g_gx[2][SS][GCOLS][BB];          // 256 MB: gx[d][t][gatecol][b]
// Double-buffered hidden state, bf16 hi/lo splits: [d][parity][split][b][k]
__device__ __align__(16) __nv_bfloat16 g_hbf[2][2][2][BB][HH];
__device__ unsigned g_bar_count[2];
__device__ unsigned g_bar_gen[2];

// bf16 split operands for the tensor-core projection
__device__ __align__(16) __nv_bfloat16 g_xhi[BB * SS * II];      // x hi
__device__ __align__(16) __nv_bfloat16 g_xlo[BB * SS * II];      // x residual
__device__ __align__(16) __nv_bfloat16 g_wthi[2 * 4 * HH * II];  // W^T (input part) hi: [d][g][c][k]
__device__ __align__(16) __nv_bfloat16 g_wtlo[2 * 4 * HH * II];  // W^T lo

struct Ptrs {
    const float* W[2][4];     // [dir][gate: i,f,g(c),o]  shape (I+H, H) row-major
    const float* bias[2][4];  // (H,)
};

// ---------------------------------------------------------------------------
// Split kernels: build bf16 hi/lo operands
// ---------------------------------------------------------------------------
__global__ void split_x_kernel(const float* __restrict__ x)
{
    int n = BB * SS * II;
    for (int i = blockIdx.x * blockDim.x + threadIdx.x; i < n; i += gridDim.x * blockDim.x) {
        float v = x[i];
        __nv_bfloat16 hi = __float2bfloat16(v);
        g_xhi[i] = hi;
        g_xlo[i] = __float2bfloat16(v - __bfloat162float(hi));
    }
}

// Transpose input-part of W (rows 0..511) into [c][k] and split to bf16 hi/lo.
__global__ void split_wt_kernel(Ptrs p)
{
    __shared__ float tile[32][33];
    const int dg = blockIdx.z;           // 0..7
    const int d  = dg >> 2;
    const int g  = dg & 3;
    const int k0 = blockIdx.x * 32;
    const int c0 = blockIdx.y * 32;
    const int tid = threadIdx.x;         // 256
    const int tx = tid & 31;
    const int ty = tid >> 5;             // 0..7

    const float* W = p.W[d][g];
#pragma unroll
    for (int r = 0; r < 4; r++) {
        int k = ty + r * 8;
        tile[k][tx] = W[(size_t)(k0 + k) * HH + c0 + tx];
    }
    __syncthreads();
#pragma unroll
    for (int r = 0; r < 4; r++) {
        int c = ty + r * 8;
        float v = tile[tx][c];
        __nv_bfloat16 hi = __float2bfloat16(v);
        size_t idx = ((size_t)(dg) * HH + c0 + c) * II + k0 + tx;
        g_wthi[idx] = hi;
        g_wtlo[idx] = __float2bfloat16(v - __bfloat162float(hi));
    }
}

// ---------------------------------------------------------------------------
// mma.sync helper (sm_80+ HMMA path; works on base sm_100 target)
// D(16x8) += A(16x16,row) * B(16x8,col), bf16 in, f32 accum.
// ---------------------------------------------------------------------------
__device__ __forceinline__ void mma16816(float* c, const uint32_t* a, const uint32_t* b)
{
    asm volatile(
        "mma.sync.aligned.m16n8k16.row.col.f32.bf16.bf16.f32 "
        "{%0,%1,%2,%3}, {%4,%5,%6,%7}, {%8,%9}, {%0,%1,%2,%3};\n"
        : "+f"(c[0]), "+f"(c[1]), "+f"(c[2]), "+f"(c[3])
        : "r"(a[0]), "r"(a[1]), "r"(a[2]), "r"(a[3]), "r"(b[0]), "r"(b[1]));
}

// ---------------------------------------------------------------------------
// Kernel A: tensor-core input projection via mma.sync (bf16-split, 3 terms)
// (unchanged from round 5 PASS)
// ---------------------------------------------------------------------------
#define PSTR 40   // padded SMEM k-stride (bf16 units): conflict-free fragments

__global__ void __launch_bounds__(256, 2) proj_mma_kernel(Ptrs p)
{
    __shared__ __nv_bfloat16 As[2][128 * PSTR];   // [hi/lo][row*PSTR + k]
    __shared__ __nv_bfloat16 Bs[2][128 * PSTR];

    const int tid  = threadIdx.x;
    const int lane = tid & 31;
    const int wid  = tid >> 5;
    const int wm   = wid >> 2;          // 0..1 (M)
    const int wn   = wid & 3;           // 0..3 (N)
    const int r    = lane >> 2;         // 0..7
    const int qc   = lane & 3;          // 0..3

    const int ct   = blockIdx.x;        // 0..15: col tile of 128 within 2048
    const int tg   = blockIdx.y;        // 0..127: pair of timesteps
    const int d    = blockIdx.z;
    const int gate = ct >> 2;
    const int hb   = (ct & 3) * 128;
    const int t0   = tg * 2;

    const __nv_bfloat16* __restrict__ wthi = &g_wthi[((size_t)(d * 4 + gate) * HH + hb) * II];
    const __nv_bfloat16* __restrict__ wtlo = &g_wtlo[((size_t)(d * 4 + gate) * HH + hb) * II];

    float acc[4][4][4];                 // [mt][nt][frag]
#pragma unroll
    for (int mt = 0; mt < 4; mt++)
#pragma unroll
        for (int nt = 0; nt < 4; nt++)
#pragma unroll
            for (int u = 0; u < 4; u++) acc[mt][nt][u] = 0.f;

    for (int ch = 0; ch < 16; ch++) {
        const int k0 = ch * 32;
        __syncthreads();
#pragma unroll
        for (int it = 0; it < 2; it++) {
            int q   = tid + it * 256;        // 0..511 float4 slots
            int row = q >> 2;
            int sl  = (q & 3) * 8;
            size_t src = (size_t)row * II + k0 + sl;
            *(float4*)&As[0][row * PSTR + sl] = *(const float4*)(wthi + src);
            *(float4*)&As[1][row * PSTR + sl] = *(const float4*)(wtlo + src);
        }
#pragma unroll
        for (int it = 0; it < 2; it++) {
            int q   = tid + it * 256;
            int row = q >> 2;
            int sl  = (q & 3) * 8;
            int b   = row & 63;
            int tl  = row >> 6;
            size_t src = ((size_t)b * SS + t0 + tl) * II + k0 + sl;
            *(float4*)&Bs[0][row * PSTR + sl] = *(const float4*)&g_xhi[src];
            *(float4*)&Bs[1][row * PSTR + sl] = *(const float4*)&g_xlo[src];
        }
        __syncthreads();

#pragma unroll
        for (int s = 0; s < 2; s++) {
            const int kb = s * 16;
            uint32_t bh[4][2], bl[4][2];
#pragma unroll
            for (int nt = 0; nt < 4; nt++) {
                int n   = wn * 32 + nt * 8 + r;
                int off = n * PSTR + kb + qc * 2;
                bh[nt][0] = *(const uint32_t*)&Bs[0][off];
                bh[nt][1] = *(const uint32_t*)&Bs[0][off + 8];
                bl[nt][0] = *(const uint32_t*)&Bs[1][off];
                bl[nt][1] = *(const uint32_t*)&Bs[1][off + 8];
            }
#pragma unroll
            for (int mt = 0; mt < 4; mt++) {
                int m   = wm * 64 + mt * 16 + r;
                int off = m * PSTR + kb + qc * 2;
                uint32_t ah[4], al[4];
                ah[0] = *(const uint32_t*)&As[0][off];
                ah[1] = *(const uint32_t*)&As[0][off + 8 * PSTR];
                ah[2] = *(const uint32_t*)&As[0][off + 8];
                ah[3] = *(const uint32_t*)&As[0][off + 8 * PSTR + 8];
                al[0] = *(const uint32_t*)&As[1][off];
                al[1] = *(const uint32_t*)&As[1][off + 8 * PSTR];
                al[2] = *(const uint32_t*)&As[1][off + 8];
                al[3] = *(const uint32_t*)&As[1][off + 8 * PSTR + 8];
#pragma unroll
                for (int nt = 0; nt < 4; nt++) {
                    mma16816(acc[mt][nt], ah, bh[nt]);   // hi*hi
                    mma16816(acc[mt][nt], ah, bl[nt]);   // hi*lo
                    mma16816(acc[mt][nt], al, bh[nt]);   // lo*hi
                }
            }
        }
    }

    const float* __restrict__ bias = p.bias[d][gate];
#pragma unroll
    for (int mt = 0; mt < 4; mt++) {
        int col0 = hb + wm * 64 + mt * 16 + r;          // within gate (0..511)
        float bv0 = bias[col0];
        float bv1 = bias[col0 + 8];
#pragma unroll
        for (int nt = 0; nt < 4; nt++) {
            int n  = wn * 32 + nt * 8 + qc * 2;
            int tl = n >> 6;
            int b  = n & 63;
            float2 v0, v1;
            v0.x = acc[mt][nt][0] + bv0;
            v0.y = acc[mt][nt][1] + bv0;
            v1.x = acc[mt][nt][2] + bv1;
            v1.y = acc[mt][nt][3] + bv1;
            *(float2*)&g_gx[d][t0 + tl][gate * 512 + col0][b]     = v0;
            *(float2*)&g_gx[d][t0 + tl][gate * 512 + col0 + 8][b] = v1;
        }
    }
}

// ---------------------------------------------------------------------------
// Grid barrier across the 64 blocks of one direction
// ---------------------------------------------------------------------------
__device__ __forceinline__ void grid_barrier(int id)
{
    __syncthreads();
    if (threadIdx.x == 0) {
        __threadfence();
        volatile unsigned* vg = &g_bar_gen[id];
        unsigned gen = *vg;
        unsigned arrived = atomicAdd(&g_bar_count[id], 1u);
        if (arrived == 63u) {
            atomicExch(&g_bar_count[id], 0u);
            __threadfence();
            *vg = gen + 1u;
        } else {
            while (*vg == gen) { __nanosleep(32); }
        }
        __threadfence();
    }
    __syncthreads();
}

// ---------------------------------------------------------------------------
// Kernel B: persistent TENSOR-CORE recurrent kernel.
// 128 blocks x 256 threads; blocks 0..63 fwd, 64..127 bwd. Block z owns 8 h
// indices (32 gate-cols c = g*8+j). Per step: D(32c x 64b) = Wh^T_slice x
// h_prev via bf16-split mma.sync (3 terms), + gx; gates; cell update; publish
// h_t as bf16 hi/lo to global; grid barrier.
// SMEM: W hi/lo [32][520], h hi/lo [64][520] (bf16), gates [32][66] f32, c[512].
// ---------------------------------------------------------------------------
#define RWSTR 520
#define R2_WHI 0
#define R2_WLO (32 * RWSTR)
#define R2_HHI (2 * 32 * RWSTR)
#define R2_HLO (2 * 32 * RWSTR + 64 * RWSTR)
#define R2_BF16_UNITS (2 * 32 * RWSTR + 2 * 64 * RWSTR)       // 99840 bf16
#define R2_GATE_BYTES (R2_BF16_UNITS * 2)                     // 199680
#define R2_C_BYTES    (R2_GATE_BYTES + 32 * 66 * 4)           // 208128
#define R2_SMEM_BYTES (R2_C_BYTES + 512 * 4)                  // 210176

__global__ void __launch_bounds__(256, 1) lstm_rec_mma_kernel(float* __restrict__ out, Ptrs p)
{
    const int blk = blockIdx.x;
    const int d   = blk >> 6;
    const int z   = blk & 63;
    const int hs0 = z * 8;
    const int tid = threadIdx.x;
    const int lane = tid & 31;
    const int wid  = tid >> 5;
    const int wm   = wid >> 2;          // 0..1
    const int wn   = wid & 3;           // 0..3
    const int r    = lane >> 2;         // 0..7
    const int qc   = lane & 3;          // 0..3

    extern __shared__ char smraw[];
    __nv_bfloat16* w_hi = (__nv_bfloat16*)smraw + R2_WHI;
    __nv_bfloat16* w_lo = (__nv_bfloat16*)smraw + R2_WLO;
    __nv_bfloat16* h_hi = (__nv_bfloat16*)smraw + R2_HHI;
    __nv_bfloat16* h_lo = (__nv_bfloat16*)smraw + R2_HLO;
    float* gate_sm = (float*)(smraw + R2_GATE_BYTES);   // [32][66]
    float* c_sm    = (float*)(smraw + R2_C_BYTES);      // [512]

    // Load + split recurrent weight slice: w[c][k], c = g*8+j
    for (int i = tid; i < 32 * 512; i += 256) {
        int c = i >> 9;
        int k = i & 511;
        int g = c >> 3;
        int j = c & 7;
        float v = p.W[d][g][(size_t)(II + k) * HH + hs0 + j];
        __nv_bfloat16 hi = __float2bfloat16(v);
        w_hi[c * RWSTR + k] = hi;
        w_lo[c * RWSTR + k] = __float2bfloat16(v - __bfloat162float(hi));
    }
    // Zero cell state and publish zero h (parity 0, both splits)
    const __nv_bfloat16 z16 = __float2bfloat16(0.f);
    for (int i = tid; i < 512; i += 256) {
        c_sm[i] = 0.f;
        int b = i >> 3;
        int j = i & 7;
        g_hbf[d][0][0][b][hs0 + j] = z16;
        g_hbf[d][0][1][b][hs0 + j] = z16;
    }
    __threadfence();
    grid_barrier(d);

    for (int s = 0; s < SS; s++) {
        const int t  = d ? (SS - 1 - s) : s;
        const int pr = s & 1;
        const int pw = pr ^ 1;

        // Stage h_prev (bf16 hi/lo) into SMEM [b][k]
#pragma unroll
        for (int it = 0; it < 16; it++) {
            int q   = tid + it * 256;     // 0..4095
            int row = q >> 6;
            int k8  = (q & 63) * 8;
            *(float4*)&h_hi[row * RWSTR + k8] = *(const float4*)&g_hbf[d][pr][0][row][k8];
            *(float4*)&h_lo[row * RWSTR + k8] = *(const float4*)&g_hbf[d][pr][1][row][k8];
        }
        __syncthreads();

        float acc[2][4];
#pragma unroll
        for (int nt = 0; nt < 2; nt++)
#pragma unroll
            for (int u = 0; u < 4; u++) acc[nt][u] = 0.f;

        const int mrow = wm * 16 + r;
#pragma unroll 8
        for (int ks = 0; ks < 32; ks++) {
            const int kb = ks * 16;
            const int aoff = mrow * RWSTR + kb + qc * 2;
            uint32_t ah[4], al[4];
            ah[0] = *(const uint32_t*)&w_hi[aoff];
            ah[1] = *(const uint32_t*)&w_hi[aoff + 8 * RWSTR];
            ah[2] = *(const uint32_t*)&w_hi[aoff + 8];
            ah[3] = *(const uint32_t*)&w_hi[aoff + 8 * RWSTR + 8];
            al[0] = *(const uint32_t*)&w_lo[aoff];
            al[1] = *(const uint32_t*)&w_lo[aoff + 8 * RWSTR];
            al[2] = *(const uint32_t*)&w_lo[aoff + 8];
            al[3] = *(const uint32_t*)&w_lo[aoff + 8 * RWSTR + 8];
#pragma unroll
            for (int nt = 0; nt < 2; nt++) {
                const int n = wn * 16 + nt * 8 + r;
                const int boff = n * RWSTR + kb + qc * 2;
                uint32_t bh[2], bl[2];
                bh[0] = *(const uint32_t*)&h_hi[boff];
                bh[1] = *(const uint32_t*)&h_hi[boff + 8];
                bl[0] = *(const uint32_t*)&h_lo[boff];
                bl[1] = *(const uint32_t*)&h_lo[boff + 8];
                mma16816(acc[nt], ah, bh);   // hi*hi
                mma16816(acc[nt], ah, bl);   // hi*lo
                mma16816(acc[nt], al, bh);   // lo*hi
            }
        }

        // Add gx and publish preacts to gate_sm[c][b]
        {
            const int c0r = wm * 16 + r;         // row of acc[.][0..1]
            const int c1r = c0r + 8;             // row of acc[.][2..3]
            const int col0 = (c0r >> 3) * 512 + hs0 + (c0r & 7);
            const int col1 = (c1r >> 3) * 512 + hs0 + (c1r & 7);
#pragma unroll
            for (int nt = 0; nt < 2; nt++) {
                const int b0 = wn * 16 + nt * 8 + qc * 2;
                float2 g0 = *(const float2*)&g_gx[d][t][col0][b0];
                float2 g1 = *(const float2*)&g_gx[d][t][col1][b0];
                float2 o0, o1;
                o0.x = acc[nt][0] + g0.x;
                o0.y = acc[nt][1] + g0.y;
                o1.x = acc[nt][2] + g1.x;
                o1.y = acc[nt][3] + g1.y;
                *(float2*)&gate_sm[c0r * 66 + b0] = o0;
                *(float2*)&gate_sm[c1r * 66 + b0] = o1;
            }
        }
        __syncthreads();

        // Cell update for 64 b x 8 j; publish h_t (bf16 hi/lo) + fp32 out
#pragma unroll
        for (int rr = 0; rr < 2; rr++) {
            int e  = tid + rr * 256;     // 0..511
            int b  = e >> 3;
            int j  = e & 7;
            float iv = gate_sm[(0 * 8 + j) * 66 + b];
            float fv = gate_sm[(1 * 8 + j) * 66 + b];
            float gv = gate_sm[(2 * 8 + j) * 66 + b];
            float ov = gate_sm[(3 * 8 + j) * 66 + b];
            iv = 1.f / (1.f + expf(-iv));
            fv = 1.f / (1.f + expf(-fv));
            ov = 1.f / (1.f + expf(-ov));
            gv = tanhf(gv);
            float cn = fv * c_sm[e] + iv * gv;
            c_sm[e] = cn;
            float hn = ov * tanhf(cn);
            __nv_bfloat16 hi = __float2bfloat16(hn);
            g_hbf[d][pw][0][b][hs0 + j] = hi;
            g_hbf[d][pw][1][b][hs0 + j] = __float2bfloat16(hn - __bfloat162float(hi));
            out[((size_t)b * SS + t) * (2 * HH) + d * HH + hs0 + j] = hn;
        }

        __threadfence();
        grid_barrier(d);
    }
}

// ---------------------------------------------------------------------------
// Launch
// ---------------------------------------------------------------------------
extern "C" void kernel_launch(void* const* d_in, const int* in_sizes, int n_in,
                              void* d_out, int out_size)
{
    (void)in_sizes; (void)n_in; (void)out_size;
    const float* x = (const float*)d_in[0];

    Ptrs p;
    for (int d = 0; d < 2; d++)
        for (int g = 0; g < 4; g++) {
            p.W[d][g]    = (const float*)d_in[1 + d * 8 + 2 * g];
            p.bias[d][g] = (const float*)d_in[1 + d * 8 + 2 * g + 1];
        }

    cudaFuncSetAttribute(lstm_rec_mma_kernel,
                         cudaFuncAttributeMaxDynamicSharedMemorySize,
                         R2_SMEM_BYTES);

    split_x_kernel<<<512, 256>>>(x);
    dim3 wgrid(16, 16, 8);
    split_wt_kernel<<<wgrid, 256>>>(p);

    dim3 pgrid(16, 128, 2);
    proj_mma_kernel<<<pgrid, 256>>>(p);

    lstm_rec_mma_kernel<<<128, 256, R2_SMEM_BYTES>>>((float*)d_out, p);
}

// round 7
// speedup vs baseline: 3.7407x; 1.0133x over previous
#include <cuda_runtime.h>
#include <cuda_bf16.h>
#include <math.h>
#include <stdint.h>

// Problem constants
#define BB 64
#define SS 256
#define II 512
#define HH 512
#define GCOLS (4*HH)          // 2048 gate-columns per direction (i,f,g,o)

// ---------------------------------------------------------------------------
// Scratch (device globals: allocation-free rule)
// ---------------------------------------------------------------------------
__device__ float g_gx[2][SS][GCOLS][BB];          // 256 MB: gx[d][t][gatecol][b]
// Double-buffered hidden state, bf16 hi/lo splits: [d][parity][split][b][k]
__device__ __align__(16) __nv_bfloat16 g_hbf[2][2][2][BB][HH];
__device__ unsigned g_bar_count[2];
__device__ unsigned g_bar_gen[2];

// bf16 split operands for the tensor-core projection
__device__ __align__(16) __nv_bfloat16 g_xhi[BB * SS * II];      // x hi
__device__ __align__(16) __nv_bfloat16 g_xlo[BB * SS * II];      // x residual
__device__ __align__(16) __nv_bfloat16 g_wthi[2 * 4 * HH * II];  // W^T (input part) hi: [d][g][c][k]
__device__ __align__(16) __nv_bfloat16 g_wtlo[2 * 4 * HH * II];  // W^T lo

struct Ptrs {
    const float* W[2][4];     // [dir][gate: i,f,g(c),o]  shape (I+H, H) row-major
    const float* bias[2][4];  // (H,)
};

// ---------------------------------------------------------------------------
// Split kernels: build bf16 hi/lo operands
// ---------------------------------------------------------------------------
__global__ void split_x_kernel(const float* __restrict__ x)
{
    int n = BB * SS * II;
    for (int i = blockIdx.x * blockDim.x + threadIdx.x; i < n; i += gridDim.x * blockDim.x) {
        float v = x[i];
        __nv_bfloat16 hi = __float2bfloat16(v);
        g_xhi[i] = hi;
        g_xlo[i] = __float2bfloat16(v - __bfloat162float(hi));
    }
}

// Transpose input-part of W (rows 0..511) into [c][k] and split to bf16 hi/lo.
__global__ void split_wt_kernel(Ptrs p)
{
    __shared__ float tile[32][33];
    const int dg = blockIdx.z;           // 0..7
    const int d  = dg >> 2;
    const int g  = dg & 3;
    const int k0 = blockIdx.x * 32;
    const int c0 = blockIdx.y * 32;
    const int tid = threadIdx.x;         // 256
    const int tx = tid & 31;
    const int ty = tid >> 5;             // 0..7

    const float* W = p.W[d][g];
#pragma unroll
    for (int r = 0; r < 4; r++) {
        int k = ty + r * 8;
        tile[k][tx] = W[(size_t)(k0 + k) * HH + c0 + tx];
    }
    __syncthreads();
#pragma unroll
    for (int r = 0; r < 4; r++) {
        int c = ty + r * 8;
        float v = tile[tx][c];
        __nv_bfloat16 hi = __float2bfloat16(v);
        size_t idx = ((size_t)(dg) * HH + c0 + c) * II + k0 + tx;
        g_wthi[idx] = hi;
        g_wtlo[idx] = __float2bfloat16(v - __bfloat162float(hi));
    }
}

// ---------------------------------------------------------------------------
// mma.sync helper (sm_80+ HMMA path; works on base sm_100 target)
// ---------------------------------------------------------------------------
__device__ __forceinline__ void mma16816(float* c, const uint32_t* a, const uint32_t* b)
{
    asm volatile(
        "mma.sync.aligned.m16n8k16.row.col.f32.bf16.bf16.f32 "
        "{%0,%1,%2,%3}, {%4,%5,%6,%7}, {%8,%9}, {%0,%1,%2,%3};\n"
        : "+f"(c[0]), "+f"(c[1]), "+f"(c[2]), "+f"(c[3])
        : "r"(a[0]), "r"(a[1]), "r"(a[2]), "r"(a[3]), "r"(b[0]), "r"(b[1]));
}

__device__ __forceinline__ void cp_async16(uint32_t smem_addr, const void* gptr)
{
    asm volatile("cp.async.cg.shared.global [%0], [%1], 16;"
                 :: "r"(smem_addr), "l"(gptr) : "memory");
}

// ---------------------------------------------------------------------------
// Kernel A: tensor-core input projection via mma.sync (bf16-split, 3 terms)
// (unchanged from round 5/6 PASS)
// ---------------------------------------------------------------------------
#define PSTR 40   // padded SMEM k-stride (bf16 units): conflict-free fragments

__global__ void __launch_bounds__(256, 2) proj_mma_kernel(Ptrs p)
{
    __shared__ __nv_bfloat16 As[2][128 * PSTR];   // [hi/lo][row*PSTR + k]
    __shared__ __nv_bfloat16 Bs[2][128 * PSTR];

    const int tid  = threadIdx.x;
    const int lane = tid & 31;
    const int wid  = tid >> 5;
    const int wm   = wid >> 2;          // 0..1 (M)
    const int wn   = wid & 3;           // 0..3 (N)
    const int r    = lane >> 2;         // 0..7
    const int qc   = lane & 3;          // 0..3

    const int ct   = blockIdx.x;        // 0..15: col tile of 128 within 2048
    const int tg   = blockIdx.y;        // 0..127: pair of timesteps
    const int d    = blockIdx.z;
    const int gate = ct >> 2;
    const int hb   = (ct & 3) * 128;
    const int t0   = tg * 2;

    const __nv_bfloat16* __restrict__ wthi = &g_wthi[((size_t)(d * 4 + gate) * HH + hb) * II];
    const __nv_bfloat16* __restrict__ wtlo = &g_wtlo[((size_t)(d * 4 + gate) * HH + hb) * II];

    float acc[4][4][4];                 // [mt][nt][frag]
#pragma unroll
    for (int mt = 0; mt < 4; mt++)
#pragma unroll
        for (int nt = 0; nt < 4; nt++)
#pragma unroll
            for (int u = 0; u < 4; u++) acc[mt][nt][u] = 0.f;

    for (int ch = 0; ch < 16; ch++) {
        const int k0 = ch * 32;
        __syncthreads();
#pragma unroll
        for (int it = 0; it < 2; it++) {
            int q   = tid + it * 256;        // 0..511 float4 slots
            int row = q >> 2;
            int sl  = (q & 3) * 8;
            size_t src = (size_t)row * II + k0 + sl;
            *(float4*)&As[0][row * PSTR + sl] = *(const float4*)(wthi + src);
            *(float4*)&As[1][row * PSTR + sl] = *(const float4*)(wtlo + src);
        }
#pragma unroll
        for (int it = 0; it < 2; it++) {
            int q   = tid + it * 256;
            int row = q >> 2;
            int sl  = (q & 3) * 8;
            int b   = row & 63;
            int tl  = row >> 6;
            size_t src = ((size_t)b * SS + t0 + tl) * II + k0 + sl;
            *(float4*)&Bs[0][row * PSTR + sl] = *(const float4*)&g_xhi[src];
            *(float4*)&Bs[1][row * PSTR + sl] = *(const float4*)&g_xlo[src];
        }
        __syncthreads();

#pragma unroll
        for (int s = 0; s < 2; s++) {
            const int kb = s * 16;
            uint32_t bh[4][2], bl[4][2];
#pragma unroll
            for (int nt = 0; nt < 4; nt++) {
                int n   = wn * 32 + nt * 8 + r;
                int off = n * PSTR + kb + qc * 2;
                bh[nt][0] = *(const uint32_t*)&Bs[0][off];
                bh[nt][1] = *(const uint32_t*)&Bs[0][off + 8];
                bl[nt][0] = *(const uint32_t*)&Bs[1][off];
                bl[nt][1] = *(const uint32_t*)&Bs[1][off + 8];
            }
#pragma unroll
            for (int mt = 0; mt < 4; mt++) {
                int m   = wm * 64 + mt * 16 + r;
                int off = m * PSTR + kb + qc * 2;
                uint32_t ah[4], al[4];
                ah[0] = *(const uint32_t*)&As[0][off];
                ah[1] = *(const uint32_t*)&As[0][off + 8 * PSTR];
                ah[2] = *(const uint32_t*)&As[0][off + 8];
                ah[3] = *(const uint32_t*)&As[0][off + 8 * PSTR + 8];
                al[0] = *(const uint32_t*)&As[1][off];
                al[1] = *(const uint32_t*)&As[1][off + 8 * PSTR];
                al[2] = *(const uint32_t*)&As[1][off + 8];
                al[3] = *(const uint32_t*)&As[1][off + 8 * PSTR + 8];
#pragma unroll
                for (int nt = 0; nt < 4; nt++) {
                    mma16816(acc[mt][nt], ah, bh[nt]);   // hi*hi
                    mma16816(acc[mt][nt], ah, bl[nt]);   // hi*lo
                    mma16816(acc[mt][nt], al, bh[nt]);   // lo*hi
                }
            }
        }
    }

    const float* __restrict__ bias = p.bias[d][gate];
#pragma unroll
    for (int mt = 0; mt < 4; mt++) {
        int col0 = hb + wm * 64 + mt * 16 + r;          // within gate (0..511)
        float bv0 = bias[col0];
        float bv1 = bias[col0 + 8];
#pragma unroll
        for (int nt = 0; nt < 4; nt++) {
            int n  = wn * 32 + nt * 8 + qc * 2;
            int tl = n >> 6;
            int b  = n & 63;
            float2 v0, v1;
            v0.x = acc[mt][nt][0] + bv0;
            v0.y = acc[mt][nt][1] + bv0;
            v1.x = acc[mt][nt][2] + bv1;
            v1.y = acc[mt][nt][3] + bv1;
            *(float2*)&g_gx[d][t0 + tl][gate * 512 + col0][b]     = v0;
            *(float2*)&g_gx[d][t0 + tl][gate * 512 + col0 + 8][b] = v1;
        }
    }
}

// ---------------------------------------------------------------------------
// Grid barrier across the 64 blocks of one direction
// ---------------------------------------------------------------------------
__device__ __forceinline__ void grid_barrier(int id)
{
    __syncthreads();
    if (threadIdx.x == 0) {
        __threadfence();
        volatile unsigned* vg = &g_bar_gen[id];
        unsigned gen = *vg;
        unsigned arrived = atomicAdd(&g_bar_count[id], 1u);
        if (arrived == 63u) {
            atomicExch(&g_bar_count[id], 0u);
            __threadfence();
            *vg = gen + 1u;
        } else {
            while (*vg == gen) { __nanosleep(32); }
        }
        __threadfence();
    }
    __syncthreads();
}

// ---------------------------------------------------------------------------
// Kernel B: persistent tensor-core recurrent kernel, v2.
// - W fragments (A side) preloaded in REGISTERS (step-invariant): no A LDS.
// - 8 warps = 2M x 2N x 2K (split-K halves k=512); SMEM reduction for pairs.
// - h staged per step via cp.async, each 4-warp k-group stages+syncs its half.
// ---------------------------------------------------------------------------
#define RWSTR 520
#define RB_HHI   0
#define RB_HLO   66560
#define RB_GATE  133120
#define RB_C     141568
#define RB_RED   143616
#define RB_SMEM_BYTES 151808

__global__ void __launch_bounds__(256, 1) lstm_rec_mma_kernel(float* __restrict__ out, Ptrs p)
{
    const int blk = blockIdx.x;
    const int d   = blk >> 6;
    const int z   = blk & 63;
    const int hs0 = z * 8;
    const int tid = threadIdx.x;
    const int lane = tid & 31;
    const int wid  = tid >> 5;
    const int wm   = wid & 1;           // M half (rows 0-15 / 16-31)
    const int wn   = (wid >> 1) & 1;    // N half (b 0-31 / 32-63)
    const int wk   = wid >> 2;          // K half (k 0-255 / 256-511)
    const int r    = lane >> 2;         // 0..7
    const int qc   = lane & 3;          // 0..3

    extern __shared__ char smraw[];
    __nv_bfloat16* h_hi = (__nv_bfloat16*)(smraw + RB_HHI);
    __nv_bfloat16* h_lo = (__nv_bfloat16*)(smraw + RB_HLO);
    float* gate_sm = (float*)(smraw + RB_GATE);   // [32][66]
    float* c_sm    = (float*)(smraw + RB_C);      // [512]
    float* red_sm  = (float*)(smraw + RB_RED);    // [4 pairs][32 lanes][16]

    // --- Init phase 1: stage W slice (bf16 hi/lo) into the h region ---
    {
        __nv_bfloat16* w_hi_t = h_hi;   // [32][RWSTR]
        __nv_bfloat16* w_lo_t = h_lo;
        for (int i = tid; i < 32 * 512; i += 256) {
            int c = i >> 9;
            int k = i & 511;
            int g = c >> 3;
            int j = c & 7;
            float v = p.W[d][g][(size_t)(II + k) * HH + hs0 + j];
            __nv_bfloat16 hi = __float2bfloat16(v);
            w_hi_t[c * RWSTR + k] = hi;
            w_lo_t[c * RWSTR + k] = __float2bfloat16(v - __bfloat162float(hi));
        }
    }
    __syncthreads();

    // --- Init phase 2: preload A fragments into registers (step-invariant) ---
    uint32_t ah[16][4], al[16][4];
    {
        const int mrow = wm * 16 + r;
        const int kbase = wk * 256;
#pragma unroll
        for (int ks = 0; ks < 16; ks++) {
            int off = mrow * RWSTR + kbase + ks * 16 + qc * 2;
            ah[ks][0] = *(const uint32_t*)&h_hi[off];
            ah[ks][1] = *(const uint32_t*)&h_hi[off + 8 * RWSTR];
            ah[ks][2] = *(const uint32_t*)&h_hi[off + 8];
            ah[ks][3] = *(const uint32_t*)&h_hi[off + 8 * RWSTR + 8];
            al[ks][0] = *(const uint32_t*)&h_lo[off];
            al[ks][1] = *(const uint32_t*)&h_lo[off + 8 * RWSTR];
            al[ks][2] = *(const uint32_t*)&h_lo[off + 8];
            al[ks][3] = *(const uint32_t*)&h_lo[off + 8 * RWSTR + 8];
        }
    }
    __syncthreads();   // h region now free for per-step staging

    // --- Init phase 3: zero cell state, publish zero h (parity 0) ---
    const __nv_bfloat16 z16 = __float2bfloat16(0.f);
    for (int i = tid; i < 512; i += 256) {
        c_sm[i] = 0.f;
        int b = i >> 3;
        int j = i & 7;
        g_hbf[d][0][0][b][hs0 + j] = z16;
        g_hbf[d][0][1][b][hs0 + j] = z16;
    }
    __threadfence();
    grid_barrier(d);

    const uint32_t smb_hhi = (uint32_t)__cvta_generic_to_shared(h_hi);
    const uint32_t smb_hlo = (uint32_t)__cvta_generic_to_shared(h_lo);

    for (int s = 0; s < SS; s++) {
        const int t  = d ? (SS - 1 - s) : s;
        const int pr = s & 1;
        const int pw = pr ^ 1;

        // Stage this k-group's half of h_prev (bf16 hi/lo) via cp.async.
        {
            const int gtid = tid & 127;          // thread within k-group
#pragma unroll
            for (int it = 0; it < 32; it++) {
                int q    = gtid + it * 128;      // 0..4095
                int spl  = q >> 11;              // 0..1
                int rem  = q & 2047;
                int row  = rem >> 5;             // 0..63
                int k8   = wk * 256 + (rem & 31) * 8;
                uint32_t dst = (spl ? smb_hlo : smb_hhi) + (uint32_t)(row * RWSTR + k8) * 2u;
                const void* src = &g_hbf[d][pr][spl][row][k8];
                cp_async16(dst, src);
            }
            asm volatile("cp.async.commit_group;" ::: "memory");
            asm volatile("cp.async.wait_group 0;" ::: "memory");
            asm volatile("bar.sync %0, 128;" :: "r"(1 + wk) : "memory");
        }

        float acc[4][4];
#pragma unroll
        for (int nt = 0; nt < 4; nt++)
#pragma unroll
            for (int u = 0; u < 4; u++) acc[nt][u] = 0.f;

        const int kbase = wk * 256;
#pragma unroll
        for (int ks = 0; ks < 16; ks++) {
            const int kb = kbase + ks * 16;
#pragma unroll
            for (int nt = 0; nt < 4; nt++) {
                const int n = wn * 32 + nt * 8 + r;
                const int boff = n * RWSTR + kb + qc * 2;
                uint32_t bh[2], bl[2];
                bh[0] = *(const uint32_t*)&h_hi[boff];
                bh[1] = *(const uint32_t*)&h_hi[boff + 8];
                bl[0] = *(const uint32_t*)&h_lo[boff];
                bl[1] = *(const uint32_t*)&h_lo[boff + 8];
                mma16816(acc[nt], ah[ks], bh);   // hi*hi
                mma16816(acc[nt], ah[ks], bl);   // hi*lo
                mma16816(acc[nt], al[ks], bh);   // lo*hi
            }
        }

        // Split-K reduction: wk=1 stores, wk=0 adds.
        float* rp = &red_sm[((wn * 2 + wm) * 32 + lane) * 16];
        if (wk == 1) {
#pragma unroll
            for (int nt = 0; nt < 4; nt++)
#pragma unroll
                for (int u = 0; u < 4; u++) rp[nt * 4 + u] = acc[nt][u];
        }
        __syncthreads();
        if (wk == 0) {
#pragma unroll
            for (int nt = 0; nt < 4; nt++)
#pragma unroll
                for (int u = 0; u < 4; u++) acc[nt][u] += rp[nt * 4 + u];

            const int c0r = wm * 16 + r;
            const int c1r = c0r + 8;
            const int col0 = (c0r >> 3) * 512 + hs0 + (c0r & 7);
            const int col1 = (c1r >> 3) * 512 + hs0 + (c1r & 7);
#pragma unroll
            for (int nt = 0; nt < 4; nt++) {
                const int b0 = wn * 32 + nt * 8 + qc * 2;
                float2 g0 = *(const float2*)&g_gx[d][t][col0][b0];
                float2 g1 = *(const float2*)&g_gx[d][t][col1][b0];
                float2 o0, o1;
                o0.x = acc[nt][0] + g0.x;
                o0.y = acc[nt][1] + g0.y;
                o1.x = acc[nt][2] + g1.x;
                o1.y = acc[nt][3] + g1.y;
                *(float2*)&gate_sm[c0r * 66 + b0] = o0;
                *(float2*)&gate_sm[c1r * 66 + b0] = o1;
            }
        }
        __syncthreads();

        // Cell update for 64 b x 8 j; publish h_t (bf16 hi/lo) + fp32 out
#pragma unroll
        for (int rr = 0; rr < 2; rr++) {
            int e  = tid + rr * 256;     // 0..511
            int b  = e >> 3;
            int j  = e & 7;
            float iv = gate_sm[(0 * 8 + j) * 66 + b];
            float fv = gate_sm[(1 * 8 + j) * 66 + b];
            float gv = gate_sm[(2 * 8 + j) * 66 + b];
            float ov = gate_sm[(3 * 8 + j) * 66 + b];
            iv = 1.f / (1.f + expf(-iv));
            fv = 1.f / (1.f + expf(-fv));
            ov = 1.f / (1.f + expf(-ov));
            gv = tanhf(gv);
            float cn = fv * c_sm[e] + iv * gv;
            c_sm[e] = cn;
            float hn = ov * tanhf(cn);
            __nv_bfloat16 hi = __float2bfloat16(hn);
            g_hbf[d][pw][0][b][hs0 + j] = hi;
            g_hbf[d][pw][1][b][hs0 + j] = __float2bfloat16(hn - __bfloat162float(hi));
            out[((size_t)b * SS + t) * (2 * HH) + d * HH + hs0 + j] = hn;
        }

        __threadfence();
        grid_barrier(d);
    }
}

// ---------------------------------------------------------------------------
// Launch
// ---------------------------------------------------------------------------
extern "C" void kernel_launch(void* const* d_in, const int* in_sizes, int n_in,
                              void* d_out, int out_size)
{
    (void)in_sizes; (void)n_in; (void)out_size;
    const float* x = (const float*)d_in[0];

    Ptrs p;
    for (int d = 0; d < 2; d++)
        for (int g = 0; g < 4; g++) {
            p.W[d][g]    = (const float*)d_in[1 + d * 8 + 2 * g];
            p.bias[d][g] = (const float*)d_in[1 + d * 8 + 2 * g + 1];
        }

    cudaFuncSetAttribute(lstm_rec_mma_kernel,
                         cudaFuncAttributeMaxDynamicSharedMemorySize,
                         RB_SMEM_BYTES);

    split_x_kernel<<<512, 256>>>(x);
    dim3 wgrid(16, 16, 8);
    split_wt_kernel<<<wgrid, 256>>>(p);

    dim3 pgrid(16, 128, 2);
    proj_mma_kernel<<<pgrid, 256>>>(p);

    lstm_rec_mma_kernel<<<128, 256, RB_SMEM_BYTES>>>((float*)d_out, p);
}

// round 9
// speedup vs baseline: 4.9065x; 1.3117x over previous
#include <cuda_runtime.h>
#include <cuda_bf16.h>
#include <math.h>
#include <stdint.h>

// Problem constants
#define BB 64
#define SS 256
#define II 512
#define HH 512
#define GCOLS (4*HH)          // 2048 gate-columns per direction (i,f,g,o)

// ---------------------------------------------------------------------------
// Scratch (device globals: allocation-free rule)
// ---------------------------------------------------------------------------
__device__ float g_gx[2][SS][GCOLS][BB];          // 256 MB: gx[d][t][gatecol][b]
// Double-buffered hidden state, bf16 hi/lo splits: [d][parity][split][b][k]
__device__ __align__(16) __nv_bfloat16 g_hbf[2][2][2][BB][HH];
__device__ unsigned g_bar_count[2];
__device__ unsigned g_bar_gen[2];

// bf16 split operands for the tensor-core projection
__device__ __align__(16) __nv_bfloat16 g_xhi[BB * SS * II];      // x hi
__device__ __align__(16) __nv_bfloat16 g_xlo[BB * SS * II];      // x residual
__device__ __align__(16) __nv_bfloat16 g_wthi[2 * 4 * HH * II];  // W^T (input part) hi: [d][g][c][k]
__device__ __align__(16) __nv_bfloat16 g_wtlo[2 * 4 * HH * II];  // W^T lo

struct Ptrs {
    const float* W[2][4];     // [dir][gate: i,f,g(c),o]  shape (I+H, H) row-major
    const float* bias[2][4];  // (H,)
};

// ---------------------------------------------------------------------------
// Helpers
// ---------------------------------------------------------------------------
__device__ __forceinline__ void mma16816(float* c, const uint32_t* a, const uint32_t* b)
{
    asm volatile(
        "mma.sync.aligned.m16n8k16.row.col.f32.bf16.bf16.f32 "
        "{%0,%1,%2,%3}, {%4,%5,%6,%7}, {%8,%9}, {%0,%1,%2,%3};\n"
        : "+f"(c[0]), "+f"(c[1]), "+f"(c[2]), "+f"(c[3])
        : "r"(a[0]), "r"(a[1]), "r"(a[2]), "r"(a[3]), "r"(b[0]), "r"(b[1]));
}

__device__ __forceinline__ void cp_async16(uint32_t smem_addr, const void* gptr)
{
    asm volatile("cp.async.cg.shared.global [%0], [%1], 16;"
                 :: "r"(smem_addr), "l"(gptr) : "memory");
}
#define CP_COMMIT() asm volatile("cp.async.commit_group;" ::: "memory")
#define CP_WAIT0()  asm volatile("cp.async.wait_group 0;" ::: "memory")
#define CP_WAIT1()  asm volatile("cp.async.wait_group 1;" ::: "memory")
#define CP_WAIT2()  asm volatile("cp.async.wait_group 2;" ::: "memory")

__device__ __forceinline__ unsigned ldg_acq(unsigned* p) {
    unsigned v;
    asm volatile("ld.acquire.gpu.u32 %0, [%1];" : "=r"(v) : "l"(p) : "memory");
    return v;
}
__device__ __forceinline__ unsigned atom_add_rel(unsigned* p, unsigned v) {
    unsigned o;
    asm volatile("atom.add.release.gpu.u32 %0, [%1], %2;" : "=r"(o) : "l"(p), "r"(v) : "memory");
    return o;
}
__device__ __forceinline__ void st_rel(unsigned* p, unsigned v) {
    asm volatile("st.release.gpu.u32 [%0], %1;" :: "l"(p), "r"(v) : "memory");
}
__device__ __forceinline__ void st_rlx(unsigned* p, unsigned v) {
    asm volatile("st.relaxed.gpu.u32 [%0], %1;" :: "l"(p), "r"(v) : "memory");
}

__device__ __forceinline__ float fsigmoid(float x) {
    x = fminf(fmaxf(x, -30.f), 30.f);
    float e = __expf(-x);
    return __fdividef(1.f, 1.f + e);
}
__device__ __forceinline__ float ftanh_(float x) {
    x = fminf(fmaxf(x, -15.f), 15.f);
    float e = __expf(-2.f * x);
    return __fdividef(1.f - e, 1.f + e);
}

// ---------------------------------------------------------------------------
// Split kernels: build bf16 hi/lo operands
// ---------------------------------------------------------------------------
__global__ void split_x_kernel(const float* __restrict__ x)
{
    int n = BB * SS * II;
    for (int i = blockIdx.x * blockDim.x + threadIdx.x; i < n; i += gridDim.x * blockDim.x) {
        float v = x[i];
        __nv_bfloat16 hi = __float2bfloat16(v);
        g_xhi[i] = hi;
        g_xlo[i] = __float2bfloat16(v - __bfloat162float(hi));
    }
}

__global__ void split_wt_kernel(Ptrs p)
{
    __shared__ float tile[32][33];
    const int dg = blockIdx.z;           // 0..7
    const int d  = dg >> 2;
    const int g  = dg & 3;
    const int k0 = blockIdx.x * 32;
    const int c0 = blockIdx.y * 32;
    const int tid = threadIdx.x;         // 256
    const int tx = tid & 31;
    const int ty = tid >> 5;             // 0..7

    const float* W = p.W[d][g];
#pragma unroll
    for (int r = 0; r < 4; r++) {
        int k = ty + r * 8;
        tile[k][tx] = W[(size_t)(k0 + k) * HH + c0 + tx];
    }
    __syncthreads();
#pragma unroll
    for (int r = 0; r < 4; r++) {
        int c = ty + r * 8;
        float v = tile[tx][c];
        __nv_bfloat16 hi = __float2bfloat16(v);
        size_t idx = ((size_t)(dg) * HH + c0 + c) * II + k0 + tx;
        g_wthi[idx] = hi;
        g_wtlo[idx] = __float2bfloat16(v - __bfloat162float(hi));
    }
}

// ---------------------------------------------------------------------------
// Kernel A: tensor-core input projection via mma.sync (bf16-split, 3 terms)
// v2: cp.async double-buffered staging (dynamic SMEM, 2 bufs x (A hi/lo + B hi/lo))
// ---------------------------------------------------------------------------
#define PSTR 40                 // padded SMEM k-stride (bf16 units)
#define PJ_T (128 * PSTR)       // elems per (buf,split) tile
#define PJ_SMEM_BYTES (8 * PJ_T * 2)   // 2 bufs x 2 splits x (A + B) = 81920 B

__global__ void __launch_bounds__(256, 2) proj_mma_kernel(Ptrs p)
{
    extern __shared__ __nv_bfloat16 psm[];
    // layout: A[buf][split][PJ_T] then B[buf][split][PJ_T]
    __nv_bfloat16* Ab = psm;
    __nv_bfloat16* Bb = psm + 4 * PJ_T;
    const uint32_t smbA = (uint32_t)__cvta_generic_to_shared(Ab);
    const uint32_t smbB = (uint32_t)__cvta_generic_to_shared(Bb);

    const int tid  = threadIdx.x;
    const int lane = tid & 31;
    const int wid  = tid >> 5;
    const int wm   = wid >> 2;          // 0..1 (M)
    const int wn   = wid & 3;           // 0..3 (N)
    const int r    = lane >> 2;         // 0..7
    const int qc   = lane & 3;          // 0..3

    const int ct   = blockIdx.x;        // 0..15
    const int tg   = blockIdx.y;        // 0..127
    const int d    = blockIdx.z;
    const int gate = ct >> 2;
    const int hb   = (ct & 3) * 128;
    const int t0   = tg * 2;

    const __nv_bfloat16* __restrict__ wthi = &g_wthi[((size_t)(d * 4 + gate) * HH + hb) * II];
    const __nv_bfloat16* __restrict__ wtlo = &g_wtlo[((size_t)(d * 4 + gate) * HH + hb) * II];

    float acc[4][4][4];
#pragma unroll
    for (int mt = 0; mt < 4; mt++)
#pragma unroll
        for (int nt = 0; nt < 4; nt++)
#pragma unroll
            for (int u = 0; u < 4; u++) acc[mt][nt][u] = 0.f;

    // stage chunk ch into buffer buf
    auto stage = [&](int ch, int buf) {
        const int k0 = ch * 32;
#pragma unroll
        for (int it = 0; it < 2; it++) {
            int q   = tid + it * 256;        // 0..511 float4 slots
            int row = q >> 2;
            int sl  = (q & 3) * 8;
            size_t src = (size_t)row * II + k0 + sl;
            cp_async16(smbA + (uint32_t)(((buf * 2 + 0) * PJ_T) + row * PSTR + sl) * 2u, wthi + src);
            cp_async16(smbA + (uint32_t)(((buf * 2 + 1) * PJ_T) + row * PSTR + sl) * 2u, wtlo + src);
        }
#pragma unroll
        for (int it = 0; it < 2; it++) {
            int q   = tid + it * 256;
            int row = q >> 2;
            int sl  = (q & 3) * 8;
            int b   = row & 63;
            int tl  = row >> 6;
            size_t src = ((size_t)b * SS + t0 + tl) * II + k0 + sl;
            cp_async16(smbB + (uint32_t)(((buf * 2 + 0) * PJ_T) + row * PSTR + sl) * 2u, &g_xhi[src]);
            cp_async16(smbB + (uint32_t)(((buf * 2 + 1) * PJ_T) + row * PSTR + sl) * 2u, &g_xlo[src]);
        }
        CP_COMMIT();
    };

    stage(0, 0);
    int buf = 0;
    for (int ch = 0; ch < 16; ch++) {
        if (ch < 15) { stage(ch + 1, buf ^ 1); CP_WAIT1(); }
        else         { CP_WAIT0(); }
        __syncthreads();

        const __nv_bfloat16* As0 = Ab + (buf * 2 + 0) * PJ_T;
        const __nv_bfloat16* As1 = Ab + (buf * 2 + 1) * PJ_T;
        const __nv_bfloat16* Bs0 = Bb + (buf * 2 + 0) * PJ_T;
        const __nv_bfloat16* Bs1 = Bb + (buf * 2 + 1) * PJ_T;

#pragma unroll
        for (int s = 0; s < 2; s++) {
            const int kb = s * 16;
            uint32_t bh[4][2], bl[4][2];
#pragma unroll
            for (int nt = 0; nt < 4; nt++) {
                int n   = wn * 32 + nt * 8 + r;
                int off = n * PSTR + kb + qc * 2;
                bh[nt][0] = *(const uint32_t*)&Bs0[off];
                bh[nt][1] = *(const uint32_t*)&Bs0[off + 8];
                bl[nt][0] = *(const uint32_t*)&Bs1[off];
                bl[nt][1] = *(const uint32_t*)&Bs1[off + 8];
            }
#pragma unroll
            for (int mt = 0; mt < 4; mt++) {
                int m   = wm * 64 + mt * 16 + r;
                int off = m * PSTR + kb + qc * 2;
                uint32_t ah[4], al[4];
                ah[0] = *(const uint32_t*)&As0[off];
                ah[1] = *(const uint32_t*)&As0[off + 8 * PSTR];
                ah[2] = *(const uint32_t*)&As0[off + 8];
                ah[3] = *(const uint32_t*)&As0[off + 8 * PSTR + 8];
                al[0] = *(const uint32_t*)&As1[off];
                al[1] = *(const uint32_t*)&As1[off + 8 * PSTR];
                al[2] = *(const uint32_t*)&As1[off + 8];
                al[3] = *(const uint32_t*)&As1[off + 8 * PSTR + 8];
#pragma unroll
                for (int nt = 0; nt < 4; nt++) {
                    mma16816(acc[mt][nt], ah, bh[nt]);   // hi*hi
                    mma16816(acc[mt][nt], ah, bl[nt]);   // hi*lo
                    mma16816(acc[mt][nt], al, bh[nt]);   // lo*hi
                }
            }
        }
        __syncthreads();
        buf ^= 1;
    }

    const float* __restrict__ bias = p.bias[d][gate];
#pragma unroll
    for (int mt = 0; mt < 4; mt++) {
        int col0 = hb + wm * 64 + mt * 16 + r;
        float bv0 = bias[col0];
        float bv1 = bias[col0 + 8];
#pragma unroll
        for (int nt = 0; nt < 4; nt++) {
            int n  = wn * 32 + nt * 8 + qc * 2;
            int tl = n >> 6;
            int b  = n & 63;
            float2 v0, v1;
            v0.x = acc[mt][nt][0] + bv0;
            v0.y = acc[mt][nt][1] + bv0;
            v1.x = acc[mt][nt][2] + bv1;
            v1.y = acc[mt][nt][3] + bv1;
            *(float2*)&g_gx[d][t0 + tl][gate * 512 + col0][b]     = v0;
            *(float2*)&g_gx[d][t0 + tl][gate * 512 + col0 + 8][b] = v1;
        }
    }
}

// ---------------------------------------------------------------------------
// Grid barrier (release/acquire; nanosleep backoff in the poll)
// ---------------------------------------------------------------------------
__device__ __forceinline__ void grid_barrier(int id)
{
    __syncthreads();
    if (threadIdx.x == 0) {
        unsigned gen = ldg_acq(&g_bar_gen[id]);
        unsigned old = atom_add_rel(&g_bar_count[id], 1u);
        if (old == 63u) {
            st_rlx(&g_bar_count[id], 0u);
            st_rel(&g_bar_gen[id], gen + 1u);
        } else {
            while (ldg_acq(&g_bar_gen[id]) == gen) { __nanosleep(32); }
        }
    }
    __syncthreads();
}

// ---------------------------------------------------------------------------
// Kernel B: persistent tensor-core recurrent kernel, v3.
// - A (W) fragments in registers; 8 warps = 2M x 2N x 2K split-K.
// - Pipelined staging: h_hi / h_lo / gx as 3 cp.async groups; pass1 (bh terms)
//   starts after h_hi only; h_lo + gx land under pass1 compute.
// - Release/acquire grid barrier; fast-math cell phase.
// ---------------------------------------------------------------------------
#define RWSTR 520
#define RB_HHI   0
#define RB_HLO   66560
#define RB_GATE  133120
#define RB_C     141568
#define RB_RED   143616
#define RB_GXS   151808
#define RB_SMEM_BYTES 160000

__global__ void __launch_bounds__(256, 1) lstm_rec_mma_kernel(float* __restrict__ out, Ptrs p)
{
    const int blk = blockIdx.x;
    const int d   = blk >> 6;
    const int z   = blk & 63;
    const int hs0 = z * 8;
    const int tid = threadIdx.x;
    const int lane = tid & 31;
    const int wid  = tid >> 5;
    const int wm   = wid & 1;           // M half
    const int wn   = (wid >> 1) & 1;    // N half
    const int wk   = wid >> 2;          // K half
    const int r    = lane >> 2;
    const int qc   = lane & 3;

    extern __shared__ char smraw[];
    __nv_bfloat16* h_hi = (__nv_bfloat16*)(smraw + RB_HHI);
    __nv_bfloat16* h_lo = (__nv_bfloat16*)(smraw + RB_HLO);
    float* gate_sm = (float*)(smraw + RB_GATE);   // [32][66]
    float* c_sm    = (float*)(smraw + RB_C);      // [512]
    float* red_sm  = (float*)(smraw + RB_RED);    // [4][32][16]
    float* gxs     = (float*)(smraw + RB_GXS);    // [32][64]

    // --- Init: stage W slice (bf16 hi/lo) into h region, preload A frags ---
    {
        for (int i = tid; i < 32 * 512; i += 256) {
            int c = i >> 9;
            int k = i & 511;
            int g = c >> 3;
            int j = c & 7;
            float v = p.W[d][g][(size_t)(II + k) * HH + hs0 + j];
            __nv_bfloat16 hi = __float2bfloat16(v);
            h_hi[c * RWSTR + k] = hi;
            h_lo[c * RWSTR + k] = __float2bfloat16(v - __bfloat162float(hi));
        }
    }
    __syncthreads();

    uint32_t ah[16][4], al[16][4];
    {
        const int mrow = wm * 16 + r;
        const int kbase = wk * 256;
#pragma unroll
        for (int ks = 0; ks < 16; ks++) {
            int off = mrow * RWSTR + kbase + ks * 16 + qc * 2;
            ah[ks][0] = *(const uint32_t*)&h_hi[off];
            ah[ks][1] = *(const uint32_t*)&h_hi[off + 8 * RWSTR];
            ah[ks][2] = *(const uint32_t*)&h_hi[off + 8];
            ah[ks][3] = *(const uint32_t*)&h_hi[off + 8 * RWSTR + 8];
            al[ks][0] = *(const uint32_t*)&h_lo[off];
            al[ks][1] = *(const uint32_t*)&h_lo[off + 8 * RWSTR];
            al[ks][2] = *(const uint32_t*)&h_lo[off + 8];
            al[ks][3] = *(const uint32_t*)&h_lo[off + 8 * RWSTR + 8];
        }
    }
    __syncthreads();   // h region now free

    const __nv_bfloat16 z16 = __float2bfloat16(0.f);
    for (int i = tid; i < 512; i += 256) {
        c_sm[i] = 0.f;
        int b = i >> 3;
        int j = i & 7;
        g_hbf[d][0][0][b][hs0 + j] = z16;
        g_hbf[d][0][1][b][hs0 + j] = z16;
    }
    grid_barrier(d);

    const uint32_t smb_hhi = (uint32_t)__cvta_generic_to_shared(h_hi);
    const uint32_t smb_hlo = (uint32_t)__cvta_generic_to_shared(h_lo);
    const uint32_t smb_gxs = (uint32_t)__cvta_generic_to_shared(gxs);

    for (int s = 0; s < SS; s++) {
        const int t  = d ? (SS - 1 - s) : s;
        const int pr = s & 1;
        const int pw = pr ^ 1;
        const int gtid = tid & 127;

        // Group 1: h_hi (own k-half)
#pragma unroll
        for (int it = 0; it < 16; it++) {
            int q   = gtid + it * 128;       // 0..2047
            int row = q >> 5;
            int k8  = wk * 256 + (q & 31) * 8;
            cp_async16(smb_hhi + (uint32_t)(row * RWSTR + k8) * 2u, &g_hbf[d][pr][0][row][k8]);
        }
        CP_COMMIT();
        // Group 2: h_lo
#pragma unroll
        for (int it = 0; it < 16; it++) {
            int q   = gtid + it * 128;
            int row = q >> 5;
            int k8  = wk * 256 + (q & 31) * 8;
            cp_async16(smb_hlo + (uint32_t)(row * RWSTR + k8) * 2u, &g_hbf[d][pr][1][row][k8]);
        }
        CP_COMMIT();
        // Group 3: gx tile (fp32 32c x 64b), all threads
#pragma unroll
        for (int it = 0; it < 2; it++) {
            int q  = tid + it * 256;         // 0..511
            int c  = q >> 4;
            int sl = (q & 15) * 4;
            int col = (c >> 3) * 512 + hs0 + (c & 7);
            cp_async16(smb_gxs + (uint32_t)(c * 64 + sl) * 4u, &g_gx[d][t][col][sl]);
        }
        CP_COMMIT();

        float acc[4][4];
#pragma unroll
        for (int nt = 0; nt < 4; nt++)
#pragma unroll
            for (int u = 0; u < 4; u++) acc[nt][u] = 0.f;

        const int kbase2 = wk * 256;

        CP_WAIT2();                          // h_hi ready
        asm volatile("bar.sync %0, 128;" :: "r"(1 + wk) : "memory");
        // pass 1: bh terms (hi*hi + lo*hi)
#pragma unroll
        for (int ks = 0; ks < 16; ks++) {
#pragma unroll
            for (int nt = 0; nt < 4; nt++) {
                const int n = wn * 32 + nt * 8 + r;
                const int boff = n * RWSTR + kbase2 + ks * 16 + qc * 2;
                uint32_t bh[2];
                bh[0] = *(const uint32_t*)&h_hi[boff];
                bh[1] = *(const uint32_t*)&h_hi[boff + 8];
                mma16816(acc[nt], ah[ks], bh);
                mma16816(acc[nt], al[ks], bh);
            }
        }
        CP_WAIT1();                          // h_lo ready
        asm volatile("bar.sync %0, 128;" :: "r"(1 + wk) : "memory");
        // pass 2: bl term (hi*lo)
#pragma unroll
        for (int ks = 0; ks < 16; ks++) {
#pragma unroll
            for (int nt = 0; nt < 4; nt++) {
                const int n = wn * 32 + nt * 8 + r;
                const int boff = n * RWSTR + kbase2 + ks * 16 + qc * 2;
                uint32_t bl[2];
                bl[0] = *(const uint32_t*)&h_lo[boff];
                bl[1] = *(const uint32_t*)&h_lo[boff + 8];
                mma16816(acc[nt], ah[ks], bl);
            }
        }
        CP_WAIT0();                          // gx ready (everywhere)

        // Split-K reduction
        float* rp = &red_sm[((wn * 2 + wm) * 32 + lane) * 16];
        if (wk == 1) {
#pragma unroll
            for (int nt = 0; nt < 4; nt++)
#pragma unroll
                for (int u = 0; u < 4; u++) rp[nt * 4 + u] = acc[nt][u];
        }
        __syncthreads();
        if (wk == 0) {
#pragma unroll
            for (int nt = 0; nt < 4; nt++)
#pragma unroll
                for (int u = 0; u < 4; u++) acc[nt][u] += rp[nt * 4 + u];

            const int c0r = wm * 16 + r;
            const int c1r = c0r + 8;
#pragma unroll
            for (int nt = 0; nt < 4; nt++) {
                const int b0 = wn * 32 + nt * 8 + qc * 2;
                float2 g0 = *(const float2*)&gxs[c0r * 64 + b0];
                float2 g1 = *(const float2*)&gxs[c1r * 64 + b0];
                float2 o0, o1;
                o0.x = acc[nt][0] + g0.x;
                o0.y = acc[nt][1] + g0.y;
                o1.x = acc[nt][2] + g1.x;
                o1.y = acc[nt][3] + g1.y;
                *(float2*)&gate_sm[c0r * 66 + b0] = o0;
                *(float2*)&gate_sm[c1r * 66 + b0] = o1;
            }
        }
        __syncthreads();

        // Cell update (fast math); publish h_t (bf16 hi/lo) + fp32 out
#pragma unroll
        for (int rr = 0; rr < 2; rr++) {
            int e  = tid + rr * 256;
            int b  = e >> 3;
            int j  = e & 7;
            float iv = gate_sm[(0 * 8 + j) * 66 + b];
            float fv = gate_sm[(1 * 8 + j) * 66 + b];
            float gv = gate_sm[(2 * 8 + j) * 66 + b];
            float ov = gate_sm[(3 * 8 + j) * 66 + b];
            iv = fsigmoid(iv);
            fv = fsigmoid(fv);
            ov = fsigmoid(ov);
            gv = ftanh_(gv);
            float cn = fv * c_sm[e] + iv * gv;
            c_sm[e] = cn;
            float hn = ov * ftanh_(cn);
            __nv_bfloat16 hi = __float2bfloat16(hn);
            g_hbf[d][pw][0][b][hs0 + j] = hi;
            g_hbf[d][pw][1][b][hs0 + j] = __float2bfloat16(hn - __bfloat162float(hi));
            out[((size_t)b * SS + t) * (2 * HH) + d * HH + hs0 + j] = hn;
        }

        grid_barrier(d);
    }
}

// ---------------------------------------------------------------------------
// Launch
// ---------------------------------------------------------------------------
extern "C" void kernel_launch(void* const* d_in, const int* in_sizes, int n_in,
                              void* d_out, int out_size)
{
    (void)in_sizes; (void)n_in; (void)out_size;
    const float* x = (const float*)d_in[0];

    Ptrs p;
    for (int d = 0; d < 2; d++)
        for (int g = 0; g < 4; g++) {
            p.W[d][g]    = (const float*)d_in[1 + d * 8 + 2 * g];
            p.bias[d][g] = (const float*)d_in[1 + d * 8 + 2 * g + 1];
        }

    cudaFuncSetAttribute(lstm_rec_mma_kernel,
                         cudaFuncAttributeMaxDynamicSharedMemorySize,
                         RB_SMEM_BYTES);
    cudaFuncSetAttribute(proj_mma_kernel,
                         cudaFuncAttributeMaxDynamicSharedMemorySize,
                         PJ_SMEM_BYTES);

    split_x_kernel<<<512, 256>>>(x);
    dim3 wgrid(16, 16, 8);
    split_wt_kernel<<<wgrid, 256>>>(p);

    dim3 pgrid(16, 128, 2);
    proj_mma_kernel<<<pgrid, 256, PJ_SMEM_BYTES>>>(p);

    lstm_rec_mma_kernel<<<128, 256, RB_SMEM_BYTES>>>((float*)d_out, p);
}